// round 8
// baseline (speedup 1.0000x reference)
#include <cuda_runtime.h>
#include <cuda_fp16.h>
#include <cstdint>
#include <math.h>

#define N_NODES 10000
#define N_EDGES 320000
#define N_GRAPHS 64
#define HID 256
#define ELL_CAP 128
#define FILL_BLOCKS 1250           // 1250*256 = 320000 edges
#define EMBED_BLOCKS 5000          // 5000*256*2 = 2 560 000 features

// ---------------- scratch (static __device__, no allocation) ----------------
__device__ __align__(16) float   g_h  [N_NODES * HID];       // fp32 residual state
__device__ __align__(16) __half2 g_hh [N_NODES * HID / 2];   // half mirror of g_h
__device__ __align__(16) __half2 g_t1h[N_NODES * HID / 2];
__device__ __align__(16) __half2 g_t2h[N_NODES * HID / 2];
__device__ int g_cur[N_NODES];          // zero at module load; re-zeroed by pool tail
__device__ __align__(16) int g_ell[N_NODES * ELL_CAP];

__device__ __forceinline__ float silu(float v) {
    return v / (1.0f + expf(-v));
}

__device__ __forceinline__ int clampi(int v, int hi) {
    return v < 0 ? 0 : (v >= hi ? hi - 1 : v);
}

__device__ __forceinline__ void mma_f16(float* d, const unsigned* a, const unsigned* b) {
    asm volatile(
        "mma.sync.aligned.m16n8k16.row.col.f32.f16.f16.f32 "
        "{%0,%1,%2,%3}, {%4,%5,%6,%7}, {%8,%9}, {%0,%1,%2,%3};"
        : "+f"(d[0]), "+f"(d[1]), "+f"(d[2]), "+f"(d[3])
        : "r"(a[0]), "r"(a[1]), "r"(a[2]), "r"(a[3]),
          "r"(b[0]), "r"(b[1]));
}

__device__ __forceinline__ void cp16(void* smem_dst, const void* gsrc, bool pred) {
    unsigned s = (unsigned)__cvta_generic_to_shared(smem_dst);
    int szn = pred ? 16 : 0;
    asm volatile("cp.async.ca.shared.global [%0], [%1], 16, %2;"
                 :: "r"(s), "l"(gsrc), "r"(szn));
}

// ------- fused setup: ELL fill (blocks [0,FILL_BLOCKS)) + embed (rest) ------
__global__ void setup_kernel(const float* __restrict__ x,
                             const float* __restrict__ w,
                             const float* __restrict__ b,
                             const int* __restrict__ src,
                             const int* __restrict__ dst) {
    int blk = blockIdx.x;
    if (blk < FILL_BLOCKS) {
        int e = blk * 256 + threadIdx.x;
        if (e < N_EDGES) {
            int d = clampi(dst[e], N_NODES);
            int slot = atomicAdd(&g_cur[d], 1);
            if (slot < ELL_CAP)
                g_ell[d * ELL_CAP + slot] = clampi(src[e], N_NODES);
        }
    } else {
        int idx2 = (blk - FILL_BLOCKS) * 256 + threadIdx.x;   // feature pair
        if (idx2 < N_NODES * HID / 2) {
            int n  = idx2 >> 7;            // /128
            int d  = (idx2 & 127) * 2;
            float xv = x[n];
            float v0 = silu(xv * w[d]     + b[d]);
            float v1 = silu(xv * w[d + 1] + b[d + 1]);
            *(float2*)(g_h + (size_t)n * HID + d) = make_float2(v0, v1);
            g_hh[idx2] = __floats2half2_rn(v0, v1);
        }
    }
}

// ------------- fp16 tensor-core GEMM: C = act(A[M,256] @ W + bias) ---------
// A half2 via cp.async double-buffer; B (fp32) converted to half2 k-pairs
// during load with register prefetch. 64x128 tile, 256 threads, 8 warps.
#define BM 64
#define BN 128
#define BK 32
#define AS2_STRIDE 20    // half2 units (80 B/row)
#define BS2_STRIDE 136   // half2 units
#define AS2_BUF (BM * AS2_STRIDE)        // 1280 half2
#define BS2_BUF (16 * BS2_STRIDE)        // 2176 half2
#define GEMMH_SMEM_BYTES ((2 * AS2_BUF + 2 * BS2_BUF) * 4)   // 27648

template <bool RELU>
__global__ __launch_bounds__(256, 3)
void gemm_fp16(const __half2* __restrict__ A,
               const float* __restrict__ W,
               const float* __restrict__ bias,
               __half2* __restrict__ Ch, int M) {
    extern __shared__ __half2 dynsmem2[];
    __half2* As2 = dynsmem2;                  // [2][BM][AS2_STRIDE]
    __half2* Bs2 = dynsmem2 + 2 * AS2_BUF;    // [2][16][BS2_STRIDE]

    int tid  = threadIdx.x;
    int lane = tid & 31;
    int warp = tid >> 5;
    int wr = (warp & 1) * 32;
    int wc = (warp >> 1) * 32;
    int rowBase = blockIdx.x * BM;
    int colBase = blockIdx.y * BN;
    int g  = lane >> 2;
    int t4 = lane & 3;

    int arow = tid >> 2;             // 0..63
    int acq  = (tid & 3) * 4;        // half2 idx 0,4,8,12
    int kp0 = tid >> 5;              // kp 0..7
    int nq0 = (tid & 31) * 4;
    int kp1 = kp0 + 8;

    float acc[2][4][4];
#pragma unroll
    for (int mi = 0; mi < 2; mi++)
#pragma unroll
        for (int ni = 0; ni < 4; ni++)
#pragma unroll
            for (int r = 0; r < 4; r++) acc[mi][ni][r] = 0.0f;

    // prologue: A tile0 cp.async, B tile0 -> regs
    {
        int grow = rowBase + arow;
        cp16(&As2[arow * AS2_STRIDE + acq],
             A + (size_t)grow * (HID / 2) + acq, grow < M);
        asm volatile("cp.async.commit_group;");
    }
    __half2 breg[2][4];
#pragma unroll
    for (int i = 0; i < 2; i++) {
        int kp = (i == 0) ? kp0 : kp1;
        float4 v0 = *(const float4*)(W + (size_t)(2 * kp    ) * HID + colBase + nq0);
        float4 v1 = *(const float4*)(W + (size_t)(2 * kp + 1) * HID + colBase + nq0);
        breg[i][0] = __floats2half2_rn(v0.x, v1.x);
        breg[i][1] = __floats2half2_rn(v0.y, v1.y);
        breg[i][2] = __floats2half2_rn(v0.z, v1.z);
        breg[i][3] = __floats2half2_rn(v0.w, v1.w);
    }

    int buf = 0;
#pragma unroll
    for (int kt = 0; kt < HID / BK; kt++) {
        asm volatile("cp.async.wait_group 0;");
        __syncthreads();                    // A(kt) visible; compute(kt-1) done

        __half2* Bd = Bs2 + buf * BS2_BUF;
        *(float4*)&Bd[kp0 * BS2_STRIDE + nq0] = *(float4*)&breg[0][0];
        *(float4*)&Bd[kp1 * BS2_STRIDE + nq0] = *(float4*)&breg[1][0];

        if (kt < HID / BK - 1) {
            int k2 = (kt + 1) * BK;
            int grow = rowBase + arow;
            cp16(&As2[(buf ^ 1) * AS2_BUF + arow * AS2_STRIDE + acq],
                 A + (size_t)grow * (HID / 2) + k2 / 2 + acq, grow < M);
            asm volatile("cp.async.commit_group;");
#pragma unroll
            for (int i = 0; i < 2; i++) {
                int kp = (i == 0) ? kp0 : kp1;
                float4 v0 = *(const float4*)(W + (size_t)(k2 + 2 * kp    ) * HID + colBase + nq0);
                float4 v1 = *(const float4*)(W + (size_t)(k2 + 2 * kp + 1) * HID + colBase + nq0);
                breg[i][0] = __floats2half2_rn(v0.x, v1.x);
                breg[i][1] = __floats2half2_rn(v0.y, v1.y);
                breg[i][2] = __floats2half2_rn(v0.z, v1.z);
                breg[i][3] = __floats2half2_rn(v0.w, v1.w);
            }
        }
        __syncthreads();                    // B(kt) STS visible

        const __half2* Ab = As2 + buf * AS2_BUF;
        const __half2* Bb = Bs2 + buf * BS2_BUF;
#pragma unroll
        for (int s = 0; s < 2; s++) {       // two k16 steps per 32-k tile
            int ko = s * 8;
            unsigned a[2][4], b[4][2];
#pragma unroll
            for (int mi = 0; mi < 2; mi++) {
                int m0 = wr + mi * 16;
                a[mi][0] = *(const unsigned*)&Ab[(m0 + g    ) * AS2_STRIDE + ko + t4    ];
                a[mi][1] = *(const unsigned*)&Ab[(m0 + g + 8) * AS2_STRIDE + ko + t4    ];
                a[mi][2] = *(const unsigned*)&Ab[(m0 + g    ) * AS2_STRIDE + ko + t4 + 4];
                a[mi][3] = *(const unsigned*)&Ab[(m0 + g + 8) * AS2_STRIDE + ko + t4 + 4];
            }
#pragma unroll
            for (int ni = 0; ni < 4; ni++) {
                int n0 = wc + ni * 8;
                b[ni][0] = *(const unsigned*)&Bb[(ko + t4    ) * BS2_STRIDE + n0 + g];
                b[ni][1] = *(const unsigned*)&Bb[(ko + t4 + 4) * BS2_STRIDE + n0 + g];
            }
#pragma unroll
            for (int mi = 0; mi < 2; mi++)
#pragma unroll
                for (int ni = 0; ni < 4; ni++)
                    mma_f16(acc[mi][ni], a[mi], b[ni]);
        }
        buf ^= 1;
    }

    // epilogue: bias (+relu) -> half2
#pragma unroll
    for (int mi = 0; mi < 2; mi++) {
        int row0 = rowBase + wr + mi * 16 + g;
        int row1 = row0 + 8;
#pragma unroll
        for (int ni = 0; ni < 4; ni++) {
            int col = colBase + wc + ni * 8 + t4 * 2;
            float b0 = bias[col], b1 = bias[col + 1];
            float v00 = acc[mi][ni][0] + b0, v01 = acc[mi][ni][1] + b1;
            float v10 = acc[mi][ni][2] + b0, v11 = acc[mi][ni][3] + b1;
            if (RELU) {
                v00 = fmaxf(v00, 0.f); v01 = fmaxf(v01, 0.f);
                v10 = fmaxf(v10, 0.f); v11 = fmaxf(v11, 0.f);
            }
            if (row0 < M)
                Ch[(size_t)row0 * (HID / 2) + (col >> 1)] = __floats2half2_rn(v00, v01);
            if (row1 < M)
                Ch[(size_t)row1 * (HID / 2) + (col >> 1)] = __floats2half2_rn(v10, v11);
        }
    }
}

// ------- edge aggregation: warp-per-node float4 gather-max ------------------
// Updates fp32 g_h AND half mirror g_hh.
__global__ void agg_kernel() {
    const unsigned FULL = 0xffffffffu;
    int warp = threadIdx.x >> 5;
    int lane = threadIdx.x & 31;
    int n = blockIdx.x * 8 + warp;
    if (n >= N_NODES) return;

    int cnt = min(g_cur[n], ELL_CAP);
    const int* lst = g_ell + n * ELL_CAP;
    const float4* t2v = (const float4*)g_t2h;   // 32 float4 per row

    unsigned ninf = 0xFC00FC00u;
    __half2 mneg = *(__half2*)&ninf;
    __half2 m[8];
#pragma unroll
    for (int q = 0; q < 8; q++) m[q] = mneg;

    for (int base = 0; base < cnt; base += 32) {
        int e = base + lane;
        int idx = (e < cnt) ? lst[e] : 0;
        int c = min(32, cnt - base);
        int j = 0;
        for (; j + 2 <= c; j += 2) {
            int s0 = __shfl_sync(FULL, idx, j);
            int s1 = __shfl_sync(FULL, idx, j + 1);
            float4 v0 = t2v[s0 * 32 + lane];
            float4 v1 = t2v[s1 * 32 + lane];
            m[0] = __hmax2(m[0], *(__half2*)&v0.x);
            m[1] = __hmax2(m[1], *(__half2*)&v0.y);
            m[2] = __hmax2(m[2], *(__half2*)&v0.z);
            m[3] = __hmax2(m[3], *(__half2*)&v0.w);
            m[4] = __hmax2(m[4], *(__half2*)&v1.x);
            m[5] = __hmax2(m[5], *(__half2*)&v1.y);
            m[6] = __hmax2(m[6], *(__half2*)&v1.z);
            m[7] = __hmax2(m[7], *(__half2*)&v1.w);
        }
        if (j < c) {
            int s0 = __shfl_sync(FULL, idx, j);
            float4 v0 = t2v[s0 * 32 + lane];
            m[0] = __hmax2(m[0], *(__half2*)&v0.x);
            m[1] = __hmax2(m[1], *(__half2*)&v0.y);
            m[2] = __hmax2(m[2], *(__half2*)&v0.z);
            m[3] = __hmax2(m[3], *(__half2*)&v0.w);
        }
    }
#pragma unroll
    for (int q = 0; q < 4; q++) m[q] = __hmax2(m[q], m[q + 4]);

    float f[8];
#pragma unroll
    for (int q = 0; q < 4; q++) {
        float2 p = __half22float2(m[q]);
        f[2 * q]     = (cnt > 0) ? p.x : 0.0f;
        f[2 * q + 1] = (cnt > 0) ? p.y : 0.0f;
    }
    float4* hp = (float4*)(g_h + (size_t)n * HID) + lane * 2;
    float4 h0 = hp[0], h1 = hp[1];
    h0.x += silu(f[0]); h0.y += silu(f[1]); h0.z += silu(f[2]); h0.w += silu(f[3]);
    h1.x += silu(f[4]); h1.y += silu(f[5]); h1.z += silu(f[6]); h1.w += silu(f[7]);
    hp[0] = h0; hp[1] = h1;

    // half mirror (lane owns 8 halves = one 16B store)
    __half2 hh[4];
    hh[0] = __floats2half2_rn(h0.x, h0.y);
    hh[1] = __floats2half2_rn(h0.z, h0.w);
    hh[2] = __floats2half2_rn(h1.x, h1.y);
    hh[3] = __floats2half2_rn(h1.z, h1.w);
    ((float4*)(g_hh + (size_t)n * (HID / 2)))[lane] = *(float4*)hh;
}

// ------- global mean pool (batch sorted) + re-zero g_cur for next call -----
__global__ void pool_kernel(const int* __restrict__ batch,
                            float* __restrict__ out) {
    int g = blockIdx.x;          // 0..63
    int tid = threadIdx.x;       // 0..255 feature

    int lo = 0, hi = N_NODES;
    while (lo < hi) { int m = (lo + hi) >> 1; if (batch[m] < g) lo = m + 1; else hi = m; }
    int start = lo;
    lo = start; hi = N_NODES;
    while (lo < hi) { int m = (lo + hi) >> 1; if (batch[m] < g + 1) lo = m + 1; else hi = m; }
    int end = lo;

    float s = 0.0f;
    for (int n = start; n < end; n++)
        s += g_h[(size_t)n * HID + tid];
    float c = (float)(end - start);
    out[g * HID + tid] = s / fmaxf(c, 1.0f);

    int z = g * 256 + tid;       // 64*256 = 16384 >= N_NODES
    if (z < N_NODES) g_cur[z] = 0;
}

// ---------------- launch ----------------
extern "C" void kernel_launch(void* const* d_in, const int* in_sizes, int n_in,
                              void* d_out, int out_size) {
    const float* x     = (const float*)d_in[0];
    const int*   ei    = (const int*)d_in[1];
    const int*   batch = (const int*)d_in[2];
    const float* W_emb = (const float*)d_in[3];
    const float* b_emb = (const float*)d_in[4];
    const float* W1a   = (const float*)d_in[5];
    const float* b1a   = (const float*)d_in[6];
    const float* W1b   = (const float*)d_in[7];
    const float* b1b   = (const float*)d_in[8];
    const float* W2a   = (const float*)d_in[9];
    const float* b2a   = (const float*)d_in[10];
    const float* W2b   = (const float*)d_in[11];
    const float* b2b   = (const float*)d_in[12];
    float* out = (float*)d_out;

    const int* src = ei;
    const int* dst = ei + N_EDGES;

    __half2* hh = nullptr; __half2* t1h = nullptr; __half2* t2h = nullptr;
    cudaGetSymbolAddress((void**)&hh,  g_hh);
    cudaGetSymbolAddress((void**)&t1h, g_t1h);
    cudaGetSymbolAddress((void**)&t2h, g_t2h);

    // setup: ELL fill + embed in one grid (overlapped)
    setup_kernel<<<FILL_BLOCKS + EMBED_BLOCKS, 256>>>(x, W_emb, b_emb, src, dst);

    dim3 ggrid((N_NODES + BM - 1) / BM, HID / BN);

    // conv 1
    gemm_fp16<true ><<<ggrid, 256, GEMMH_SMEM_BYTES>>>(hh,  W1a, b1a, t1h, N_NODES);
    gemm_fp16<false><<<ggrid, 256, GEMMH_SMEM_BYTES>>>(t1h, W1b, b1b, t2h, N_NODES);
    agg_kernel<<<1250, 256>>>();

    // conv 2
    gemm_fp16<true ><<<ggrid, 256, GEMMH_SMEM_BYTES>>>(hh,  W2a, b2a, t1h, N_NODES);
    gemm_fp16<false><<<ggrid, 256, GEMMH_SMEM_BYTES>>>(t1h, W2b, b2b, t2h, N_NODES);
    agg_kernel<<<1250, 256>>>();

    // global mean pool (+ g_cur re-zero for next call)
    pool_kernel<<<N_GRAPHS, 256>>>(batch, out);
}

// round 9
// speedup vs baseline: 1.2514x; 1.2514x over previous
#include <cuda_runtime.h>
#include <cuda_fp16.h>
#include <cstdint>
#include <math.h>

#define N_NODES 10000
#define N_EDGES 320000
#define N_GRAPHS 64
#define HID 256
#define ELL_CAP 128
#define FILL_BLOCKS 1250           // 1250*256 = 320000 edges

// ---------------- scratch (static __device__, no allocation) ----------------
__device__ __align__(16) float   g_h  [N_NODES * HID];
__device__ __align__(16) __half2 g_t1h[N_NODES * HID / 2];
__device__ __align__(16) __half2 g_t2h[N_NODES * HID / 2];
__device__ int g_cur[N_NODES];          // zero at module load; re-zeroed by pool tail
__device__ __align__(16) int g_ell[N_NODES * ELL_CAP];

__device__ __forceinline__ float silu(float v) {
    return v / (1.0f + expf(-v));
}

__device__ __forceinline__ int clampi(int v, int hi) {
    return v < 0 ? 0 : (v >= hi ? hi - 1 : v);
}

__device__ __forceinline__ unsigned f2tf32(float f) {
    unsigned r;
    asm("cvt.rna.tf32.f32 %0, %1;" : "=r"(r) : "f"(f));
    return r;
}

__device__ __forceinline__ void mma_tf32(float* d, const unsigned* a, const unsigned* b) {
    asm volatile(
        "mma.sync.aligned.m16n8k8.row.col.f32.tf32.tf32.f32 "
        "{%0,%1,%2,%3}, {%4,%5,%6,%7}, {%8,%9}, {%0,%1,%2,%3};"
        : "+f"(d[0]), "+f"(d[1]), "+f"(d[2]), "+f"(d[3])
        : "r"(a[0]), "r"(a[1]), "r"(a[2]), "r"(a[3]),
          "r"(b[0]), "r"(b[1]));
}

__device__ __forceinline__ void mma_f16(float* d, const unsigned* a, const unsigned* b) {
    asm volatile(
        "mma.sync.aligned.m16n8k16.row.col.f32.f16.f16.f32 "
        "{%0,%1,%2,%3}, {%4,%5,%6,%7}, {%8,%9}, {%0,%1,%2,%3};"
        : "+f"(d[0]), "+f"(d[1]), "+f"(d[2]), "+f"(d[3])
        : "r"(a[0]), "r"(a[1]), "r"(a[2]), "r"(a[3]),
          "r"(b[0]), "r"(b[1]));
}

__device__ __forceinline__ void cp16(void* smem_dst, const void* gsrc, bool pred) {
    unsigned s = (unsigned)__cvta_generic_to_shared(smem_dst);
    int szn = pred ? 16 : 0;
    asm volatile("cp.async.ca.shared.global [%0], [%1], 16, %2;"
                 :: "r"(s), "l"(gsrc), "r"(szn));
}

// ------- fused setup: ELL fill (blocks [0,FILL_BLOCKS)) + embed (rest) ------
__global__ void setup_kernel(const float* __restrict__ x,
                             const float* __restrict__ w,
                             const float* __restrict__ b,
                             const int* __restrict__ src,
                             const int* __restrict__ dst) {
    int blk = blockIdx.x;
    if (blk < FILL_BLOCKS) {
        int e = blk * 256 + threadIdx.x;
        if (e < N_EDGES) {
            int d = clampi(dst[e], N_NODES);
            int slot = atomicAdd(&g_cur[d], 1);
            if (slot < ELL_CAP)
                g_ell[d * ELL_CAP + slot] = clampi(src[e], N_NODES);
        }
    } else {
        int idx = (blk - FILL_BLOCKS) * 256 + threadIdx.x;
        if (idx < N_NODES * HID) {
            int n = idx >> 8;
            int d = idx & 255;
            g_h[idx] = silu(x[n] * w[d] + b[d]);
        }
    }
}

// ------------- GEMM-a (tf32): t1h = relu(h[M,256] @ W + bias) as half2 -----
#define BM 64
#define BN 128
#define BK 32
#define AS_STRIDE 36
#define BS_STRIDE 136
#define AS_BUF (BM * AS_STRIDE)   // 2304 floats
#define BS_BUF (BK * BS_STRIDE)   // 4352 floats
#define GEMM_SMEM_BYTES ((2 * AS_BUF + 2 * BS_BUF) * 4)   // 53248

__global__ __launch_bounds__(256, 3)
void gemm_tf32(const float* __restrict__ A,
               const float* __restrict__ W,
               const float* __restrict__ bias,
               __half2* __restrict__ Ch, int M) {
    extern __shared__ float dynsmem[];
    float* As = dynsmem;                 // [2][BM][AS_STRIDE]
    float* Bs = dynsmem + 2 * AS_BUF;    // [2][BK][BS_STRIDE]

    int tid  = threadIdx.x;
    int lane = tid & 31;
    int warp = tid >> 5;
    int wr = (warp & 1) * 32;
    int wc = (warp >> 1) * 32;
    int rowBase = blockIdx.x * BM;
    int colBase = blockIdx.y * BN;
    int g  = lane >> 2;
    int t4 = lane & 3;

    int ar[2], ac[2], br[4], bc[4];
#pragma unroll
    for (int i = 0; i < 2; i++) {
        int l = tid + 256 * i;
        ar[i] = l >> 3;  ac[i] = (l & 7) * 4;
    }
#pragma unroll
    for (int i = 0; i < 4; i++) {
        int l = tid + 256 * i;
        br[i] = l >> 5;  bc[i] = (l & 31) * 4;
    }

    float acc[2][4][4];
#pragma unroll
    for (int mi = 0; mi < 2; mi++)
#pragma unroll
        for (int ni = 0; ni < 4; ni++)
#pragma unroll
            for (int r = 0; r < 4; r++) acc[mi][ni][r] = 0.0f;

#pragma unroll
    for (int i = 0; i < 2; i++) {
        int grow = rowBase + ar[i];
        cp16(&As[ar[i] * AS_STRIDE + ac[i]],
             A + (size_t)grow * HID + ac[i], grow < M);
    }
#pragma unroll
    for (int i = 0; i < 4; i++)
        cp16(&Bs[br[i] * BS_STRIDE + bc[i]],
             W + (size_t)br[i] * HID + colBase + bc[i], true);
    asm volatile("cp.async.commit_group;");

    int buf = 0;
#pragma unroll
    for (int kt = 0; kt < HID / BK; kt++) {
        asm volatile("cp.async.wait_group 0;");
        __syncthreads();

        if (kt < HID / BK - 1) {
            int k2 = (kt + 1) * BK;
            float* Ad = As + (buf ^ 1) * AS_BUF;
            float* Bd = Bs + (buf ^ 1) * BS_BUF;
#pragma unroll
            for (int i = 0; i < 2; i++) {
                int grow = rowBase + ar[i];
                cp16(&Ad[ar[i] * AS_STRIDE + ac[i]],
                     A + (size_t)grow * HID + k2 + ac[i], grow < M);
            }
#pragma unroll
            for (int i = 0; i < 4; i++)
                cp16(&Bd[br[i] * BS_STRIDE + bc[i]],
                     W + (size_t)(k2 + br[i]) * HID + colBase + bc[i], true);
            asm volatile("cp.async.commit_group;");
        }

        const float* Ab = As + buf * AS_BUF;
        const float* Bb = Bs + buf * BS_BUF;
#pragma unroll
        for (int s = 0; s < 4; s++) {
            int k0 = s * 8;
            unsigned a[2][4], b[4][2];
#pragma unroll
            for (int mi = 0; mi < 2; mi++) {
                int m0 = wr + mi * 16;
                a[mi][0] = f2tf32(Ab[(m0 + g    ) * AS_STRIDE + k0 + t4    ]);
                a[mi][1] = f2tf32(Ab[(m0 + g + 8) * AS_STRIDE + k0 + t4    ]);
                a[mi][2] = f2tf32(Ab[(m0 + g    ) * AS_STRIDE + k0 + t4 + 4]);
                a[mi][3] = f2tf32(Ab[(m0 + g + 8) * AS_STRIDE + k0 + t4 + 4]);
            }
#pragma unroll
            for (int ni = 0; ni < 4; ni++) {
                int n0 = wc + ni * 8;
                b[ni][0] = f2tf32(Bb[(k0 + t4    ) * BS_STRIDE + n0 + g]);
                b[ni][1] = f2tf32(Bb[(k0 + t4 + 4) * BS_STRIDE + n0 + g]);
            }
#pragma unroll
            for (int mi = 0; mi < 2; mi++)
#pragma unroll
                for (int ni = 0; ni < 4; ni++)
                    mma_tf32(acc[mi][ni], a[mi], b[ni]);
        }
        buf ^= 1;
    }

    // epilogue: bias + relu -> half2
#pragma unroll
    for (int mi = 0; mi < 2; mi++) {
        int row0 = rowBase + wr + mi * 16 + g;
        int row1 = row0 + 8;
#pragma unroll
        for (int ni = 0; ni < 4; ni++) {
            int col = colBase + wc + ni * 8 + t4 * 2;
            float b0 = bias[col], b1 = bias[col + 1];
            float v00 = fmaxf(acc[mi][ni][0] + b0, 0.f);
            float v01 = fmaxf(acc[mi][ni][1] + b1, 0.f);
            float v10 = fmaxf(acc[mi][ni][2] + b0, 0.f);
            float v11 = fmaxf(acc[mi][ni][3] + b1, 0.f);
            if (row0 < M)
                Ch[(size_t)row0 * (HID / 2) + (col >> 1)] = __floats2half2_rn(v00, v01);
            if (row1 < M)
                Ch[(size_t)row1 * (HID / 2) + (col >> 1)] = __floats2half2_rn(v10, v11);
        }
    }
}

// ------------- GEMM-b (fp16): t2h = t1h[M,256] @ W + bias -----------------
#define AS2_STRIDE 20    // half2 units (80 B/row)
#define BS2_STRIDE 136   // half2 units
#define AS2_BUF (BM * AS2_STRIDE)        // 1280 half2
#define BS2_BUF (16 * BS2_STRIDE)        // 2176 half2
#define GEMMH_SMEM_BYTES ((2 * AS2_BUF + 2 * BS2_BUF) * 4)   // 27648

__global__ __launch_bounds__(256, 3)
void gemm_fp16(const __half2* __restrict__ A,
               const float* __restrict__ W,
               const float* __restrict__ bias,
               __half2* __restrict__ Ch, int M) {
    extern __shared__ __half2 dynsmem2[];
    __half2* As2 = dynsmem2;                  // [2][BM][AS2_STRIDE]
    __half2* Bs2 = dynsmem2 + 2 * AS2_BUF;    // [2][16][BS2_STRIDE]

    int tid  = threadIdx.x;
    int lane = tid & 31;
    int warp = tid >> 5;
    int wr = (warp & 1) * 32;
    int wc = (warp >> 1) * 32;
    int rowBase = blockIdx.x * BM;
    int colBase = blockIdx.y * BN;
    int g  = lane >> 2;
    int t4 = lane & 3;

    int arow = tid >> 2;             // 0..63
    int acq  = (tid & 3) * 4;        // half2 idx 0,4,8,12
    int kp0 = tid >> 5;              // kp 0..7
    int nq0 = (tid & 31) * 4;
    int kp1 = kp0 + 8;

    float acc[2][4][4];
#pragma unroll
    for (int mi = 0; mi < 2; mi++)
#pragma unroll
        for (int ni = 0; ni < 4; ni++)
#pragma unroll
            for (int r = 0; r < 4; r++) acc[mi][ni][r] = 0.0f;

    {
        int grow = rowBase + arow;
        cp16(&As2[arow * AS2_STRIDE + acq],
             A + (size_t)grow * (HID / 2) + acq, grow < M);
        asm volatile("cp.async.commit_group;");
    }
    __half2 breg[2][4];
#pragma unroll
    for (int i = 0; i < 2; i++) {
        int kp = (i == 0) ? kp0 : kp1;
        float4 v0 = *(const float4*)(W + (size_t)(2 * kp    ) * HID + colBase + nq0);
        float4 v1 = *(const float4*)(W + (size_t)(2 * kp + 1) * HID + colBase + nq0);
        breg[i][0] = __floats2half2_rn(v0.x, v1.x);
        breg[i][1] = __floats2half2_rn(v0.y, v1.y);
        breg[i][2] = __floats2half2_rn(v0.z, v1.z);
        breg[i][3] = __floats2half2_rn(v0.w, v1.w);
    }

    int buf = 0;
#pragma unroll
    for (int kt = 0; kt < HID / BK; kt++) {
        asm volatile("cp.async.wait_group 0;");
        __syncthreads();

        __half2* Bd = Bs2 + buf * BS2_BUF;
        *(float4*)&Bd[kp0 * BS2_STRIDE + nq0] = *(float4*)&breg[0][0];
        *(float4*)&Bd[kp1 * BS2_STRIDE + nq0] = *(float4*)&breg[1][0];

        if (kt < HID / BK - 1) {
            int k2 = (kt + 1) * BK;
            int grow = rowBase + arow;
            cp16(&As2[(buf ^ 1) * AS2_BUF + arow * AS2_STRIDE + acq],
                 A + (size_t)grow * (HID / 2) + k2 / 2 + acq, grow < M);
            asm volatile("cp.async.commit_group;");
#pragma unroll
            for (int i = 0; i < 2; i++) {
                int kp = (i == 0) ? kp0 : kp1;
                float4 v0 = *(const float4*)(W + (size_t)(k2 + 2 * kp    ) * HID + colBase + nq0);
                float4 v1 = *(const float4*)(W + (size_t)(k2 + 2 * kp + 1) * HID + colBase + nq0);
                breg[i][0] = __floats2half2_rn(v0.x, v1.x);
                breg[i][1] = __floats2half2_rn(v0.y, v1.y);
                breg[i][2] = __floats2half2_rn(v0.z, v1.z);
                breg[i][3] = __floats2half2_rn(v0.w, v1.w);
            }
        }
        __syncthreads();

        const __half2* Ab = As2 + buf * AS2_BUF;
        const __half2* Bb = Bs2 + buf * BS2_BUF;
#pragma unroll
        for (int s = 0; s < 2; s++) {
            int ko = s * 8;
            unsigned a[2][4], b[4][2];
#pragma unroll
            for (int mi = 0; mi < 2; mi++) {
                int m0 = wr + mi * 16;
                a[mi][0] = *(const unsigned*)&Ab[(m0 + g    ) * AS2_STRIDE + ko + t4    ];
                a[mi][1] = *(const unsigned*)&Ab[(m0 + g + 8) * AS2_STRIDE + ko + t4    ];
                a[mi][2] = *(const unsigned*)&Ab[(m0 + g    ) * AS2_STRIDE + ko + t4 + 4];
                a[mi][3] = *(const unsigned*)&Ab[(m0 + g + 8) * AS2_STRIDE + ko + t4 + 4];
            }
#pragma unroll
            for (int ni = 0; ni < 4; ni++) {
                int n0 = wc + ni * 8;
                b[ni][0] = *(const unsigned*)&Bb[(ko + t4    ) * BS2_STRIDE + n0 + g];
                b[ni][1] = *(const unsigned*)&Bb[(ko + t4 + 4) * BS2_STRIDE + n0 + g];
            }
#pragma unroll
            for (int mi = 0; mi < 2; mi++)
#pragma unroll
                for (int ni = 0; ni < 4; ni++)
                    mma_f16(acc[mi][ni], a[mi], b[ni]);
        }
        buf ^= 1;
    }

    // epilogue: bias (no relu) -> half2
#pragma unroll
    for (int mi = 0; mi < 2; mi++) {
        int row0 = rowBase + wr + mi * 16 + g;
        int row1 = row0 + 8;
#pragma unroll
        for (int ni = 0; ni < 4; ni++) {
            int col = colBase + wc + ni * 8 + t4 * 2;
            float b0 = bias[col], b1 = bias[col + 1];
            if (row0 < M)
                Ch[(size_t)row0 * (HID / 2) + (col >> 1)] =
                    __floats2half2_rn(acc[mi][ni][0] + b0, acc[mi][ni][1] + b1);
            if (row1 < M)
                Ch[(size_t)row1 * (HID / 2) + (col >> 1)] =
                    __floats2half2_rn(acc[mi][ni][2] + b0, acc[mi][ni][3] + b1);
        }
    }
}

// ------- edge aggregation: warp-per-node float4 gather-max, 4-deep ILP ------
__global__ void agg_kernel() {
    const unsigned FULL = 0xffffffffu;
    int warp = threadIdx.x >> 5;
    int lane = threadIdx.x & 31;
    int n = blockIdx.x * 8 + warp;
    if (n >= N_NODES) return;

    int cnt = min(g_cur[n], ELL_CAP);
    const int* lst = g_ell + n * ELL_CAP;
    const float4* t2v = (const float4*)g_t2h;   // 32 float4 per row

    unsigned ninf = 0xFC00FC00u;
    __half2 mneg = *(__half2*)&ninf;
    __half2 m[8];
#pragma unroll
    for (int q = 0; q < 8; q++) m[q] = mneg;

    for (int base = 0; base < cnt; base += 32) {
        int e = base + lane;
        int idx = (e < cnt) ? lst[e] : 0;
        int c = min(32, cnt - base);
        int j = 0;
        for (; j + 4 <= c; j += 4) {
            int s0 = __shfl_sync(FULL, idx, j);
            int s1 = __shfl_sync(FULL, idx, j + 1);
            int s2 = __shfl_sync(FULL, idx, j + 2);
            int s3 = __shfl_sync(FULL, idx, j + 3);
            float4 v0 = t2v[s0 * 32 + lane];
            float4 v1 = t2v[s1 * 32 + lane];
            float4 v2 = t2v[s2 * 32 + lane];
            float4 v3 = t2v[s3 * 32 + lane];
            m[0] = __hmax2(m[0], *(__half2*)&v0.x);
            m[1] = __hmax2(m[1], *(__half2*)&v0.y);
            m[2] = __hmax2(m[2], *(__half2*)&v0.z);
            m[3] = __hmax2(m[3], *(__half2*)&v0.w);
            m[4] = __hmax2(m[4], *(__half2*)&v1.x);
            m[5] = __hmax2(m[5], *(__half2*)&v1.y);
            m[6] = __hmax2(m[6], *(__half2*)&v1.z);
            m[7] = __hmax2(m[7], *(__half2*)&v1.w);
            m[0] = __hmax2(m[0], *(__half2*)&v2.x);
            m[1] = __hmax2(m[1], *(__half2*)&v2.y);
            m[2] = __hmax2(m[2], *(__half2*)&v2.z);
            m[3] = __hmax2(m[3], *(__half2*)&v2.w);
            m[4] = __hmax2(m[4], *(__half2*)&v3.x);
            m[5] = __hmax2(m[5], *(__half2*)&v3.y);
            m[6] = __hmax2(m[6], *(__half2*)&v3.z);
            m[7] = __hmax2(m[7], *(__half2*)&v3.w);
        }
        for (; j < c; j++) {
            int s0 = __shfl_sync(FULL, idx, j);
            float4 v0 = t2v[s0 * 32 + lane];
            m[0] = __hmax2(m[0], *(__half2*)&v0.x);
            m[1] = __hmax2(m[1], *(__half2*)&v0.y);
            m[2] = __hmax2(m[2], *(__half2*)&v0.z);
            m[3] = __hmax2(m[3], *(__half2*)&v0.w);
        }
    }
#pragma unroll
    for (int q = 0; q < 4; q++) m[q] = __hmax2(m[q], m[q + 4]);

    float f[8];
#pragma unroll
    for (int q = 0; q < 4; q++) {
        float2 p = __half22float2(m[q]);
        f[2 * q]     = (cnt > 0) ? p.x : 0.0f;
        f[2 * q + 1] = (cnt > 0) ? p.y : 0.0f;
    }
    float4* hp = (float4*)(g_h + (size_t)n * HID) + lane * 2;
    float4 h0 = hp[0], h1 = hp[1];
    h0.x += silu(f[0]); h0.y += silu(f[1]); h0.z += silu(f[2]); h0.w += silu(f[3]);
    h1.x += silu(f[4]); h1.y += silu(f[5]); h1.z += silu(f[6]); h1.w += silu(f[7]);
    hp[0] = h0; hp[1] = h1;
}

// ------- global mean pool (batch sorted) + re-zero g_cur for next call -----
__global__ void pool_kernel(const int* __restrict__ batch,
                            float* __restrict__ out) {
    int g = blockIdx.x;          // 0..63
    int tid = threadIdx.x;       // 0..255 feature

    int lo = 0, hi = N_NODES;
    while (lo < hi) { int m = (lo + hi) >> 1; if (batch[m] < g) lo = m + 1; else hi = m; }
    int start = lo;
    lo = start; hi = N_NODES;
    while (lo < hi) { int m = (lo + hi) >> 1; if (batch[m] < g + 1) lo = m + 1; else hi = m; }
    int end = lo;

    float s = 0.0f;
    for (int n = start; n < end; n++)
        s += g_h[(size_t)n * HID + tid];
    float c = (float)(end - start);
    out[g * HID + tid] = s / fmaxf(c, 1.0f);

    int z = g * 256 + tid;       // 64*256 = 16384 >= N_NODES
    if (z < N_NODES) g_cur[z] = 0;
}

// ---------------- launch ----------------
extern "C" void kernel_launch(void* const* d_in, const int* in_sizes, int n_in,
                              void* d_out, int out_size) {
    const float* x     = (const float*)d_in[0];
    const int*   ei    = (const int*)d_in[1];
    const int*   batch = (const int*)d_in[2];
    const float* W_emb = (const float*)d_in[3];
    const float* b_emb = (const float*)d_in[4];
    const float* W1a   = (const float*)d_in[5];
    const float* b1a   = (const float*)d_in[6];
    const float* W1b   = (const float*)d_in[7];
    const float* b1b   = (const float*)d_in[8];
    const float* W2a   = (const float*)d_in[9];
    const float* b2a   = (const float*)d_in[10];
    const float* W2b   = (const float*)d_in[11];
    const float* b2b   = (const float*)d_in[12];
    float* out = (float*)d_out;

    const int* src = ei;
    const int* dst = ei + N_EDGES;

    float* h = nullptr; __half2* t1h = nullptr; __half2* t2h = nullptr;
    cudaGetSymbolAddress((void**)&h,   g_h);
    cudaGetSymbolAddress((void**)&t1h, g_t1h);
    cudaGetSymbolAddress((void**)&t2h, g_t2h);

    cudaFuncSetAttribute((const void*)gemm_tf32,
        cudaFuncAttributeMaxDynamicSharedMemorySize, GEMM_SMEM_BYTES);

    // setup: ELL fill + embed in one grid (overlapped)
    int embed_blocks = (N_NODES * HID + 255) / 256;
    setup_kernel<<<FILL_BLOCKS + embed_blocks, 256>>>(x, W_emb, b_emb, src, dst);

    dim3 ggrid((N_NODES + BM - 1) / BM, HID / BN);

    // conv 1
    gemm_tf32<<<ggrid, 256, GEMM_SMEM_BYTES>>>(h, W1a, b1a, t1h, N_NODES);
    gemm_fp16<<<ggrid, 256, GEMMH_SMEM_BYTES>>>(t1h, W1b, b1b, t2h, N_NODES);
    agg_kernel<<<1250, 256>>>();

    // conv 2
    gemm_tf32<<<ggrid, 256, GEMM_SMEM_BYTES>>>(h, W2a, b2a, t1h, N_NODES);
    gemm_fp16<<<ggrid, 256, GEMMH_SMEM_BYTES>>>(t1h, W2b, b2b, t2h, N_NODES);
    agg_kernel<<<1250, 256>>>();

    // global mean pool (+ g_cur re-zero for next call)
    pool_kernel<<<N_GRAPHS, 256>>>(batch, out);
}

// round 10
// speedup vs baseline: 1.3188x; 1.0539x over previous
#include <cuda_runtime.h>
#include <cuda_fp16.h>
#include <cstdint>
#include <math.h>

#define N_NODES 10000
#define N_EDGES 320000
#define N_GRAPHS 64
#define HID 256
#define ELL_CAP 128
#define FILL_BLOCKS 1250           // 1250*256 = 320000 edges

// ---------------- scratch (static __device__, no allocation) ----------------
__device__ __align__(16) float   g_h  [N_NODES * HID];
__device__ __align__(16) __half2 g_t2h[N_NODES * HID / 2];
__device__ int g_cur[N_NODES];          // zero at module load; re-zeroed by pool tail
__device__ __align__(16) int g_ell[N_NODES * ELL_CAP];

__device__ __forceinline__ float silu(float v) {
    return v / (1.0f + expf(-v));
}

__device__ __forceinline__ int clampi(int v, int hi) {
    return v < 0 ? 0 : (v >= hi ? hi - 1 : v);
}

__device__ __forceinline__ void mma_f16(float* d, const unsigned* a, const unsigned* b) {
    asm volatile(
        "mma.sync.aligned.m16n8k16.row.col.f32.f16.f16.f32 "
        "{%0,%1,%2,%3}, {%4,%5,%6,%7}, {%8,%9}, {%0,%1,%2,%3};"
        : "+f"(d[0]), "+f"(d[1]), "+f"(d[2]), "+f"(d[3])
        : "r"(a[0]), "r"(a[1]), "r"(a[2]), "r"(a[3]),
          "r"(b[0]), "r"(b[1]));
}

// ------- fused setup: ELL fill (blocks [0,FILL_BLOCKS)) + embed (rest) ------
__global__ void setup_kernel(const float* __restrict__ x,
                             const float* __restrict__ w,
                             const float* __restrict__ b,
                             const int* __restrict__ src,
                             const int* __restrict__ dst) {
    int blk = blockIdx.x;
    if (blk < FILL_BLOCKS) {
        int e = blk * 256 + threadIdx.x;
        if (e < N_EDGES) {
            int d = clampi(dst[e], N_NODES);
            int slot = atomicAdd(&g_cur[d], 1);
            if (slot < ELL_CAP)
                g_ell[d * ELL_CAP + slot] = clampi(src[e], N_NODES);
        }
    } else {
        int idx = (blk - FILL_BLOCKS) * 256 + threadIdx.x;
        if (idx < N_NODES * HID) {
            int n = idx >> 8;
            int d = idx & 255;
            g_h[idx] = silu(x[n] * w[d] + b[d]);
        }
    }
}

// ---------------- fused conv: t2h = (relu(h@Wa+ba))@Wb + bb -----------------
// One block: 64 rows x full 256 cols. 512 threads (16 warps; warp = 16x64).
// A converted fp32->half once into smem; stage-1 result (C1) overwrites the
// A buffer; W tiles streamed with register prefetch + double-buffered smem.
#define FBM 64
#define FAS 132                    // half2 per A/C1 row (128 + 4)
#define FBS 264                    // half2 per B row (256 + 8 -> stride%32==8, conflict-free frags)
#define FA_HALF2 (FBM * FAS)       // 8448
#define FB_HALF2 (16 * FBS)        // 4224 per buffer
#define FUSED_SMEM ((FA_HALF2 + 2 * FB_HALF2) * 4)   // 67584 bytes

__device__ __forceinline__ void loadB_regs(const float* __restrict__ W, int k2,
                                           int kp, int nq, __half2 br[2][4]) {
#pragma unroll
    for (int i = 0; i < 2; i++) {
        int n = nq + i * 128;
        float4 v0 = *(const float4*)(W + (size_t)(k2 + 2 * kp)     * HID + n);
        float4 v1 = *(const float4*)(W + (size_t)(k2 + 2 * kp + 1) * HID + n);
        br[i][0] = __floats2half2_rn(v0.x, v1.x);
        br[i][1] = __floats2half2_rn(v0.y, v1.y);
        br[i][2] = __floats2half2_rn(v0.z, v1.z);
        br[i][3] = __floats2half2_rn(v0.w, v1.w);
    }
}

__device__ __forceinline__ void stsB(__half2* Bd, int kp, int nq, __half2 br[2][4]) {
    *(float4*)&Bd[kp * FBS + nq]       = *(float4*)&br[0][0];
    *(float4*)&Bd[kp * FBS + nq + 128] = *(float4*)&br[1][0];
}

__device__ __forceinline__ void compute_tile(const __half2* __restrict__ As,
                                             const __half2* __restrict__ Bb,
                                             int kbase, int wr, int wc, int g, int t4,
                                             float acc[8][4]) {
#pragma unroll
    for (int s = 0; s < 2; s++) {
        int ko = kbase + s * 8;      // half2 offset into full 128-half2 A row
        int kb = s * 8;              // tile-local B row base (k-pair units)
        unsigned a[4];
        a[0] = *(const unsigned*)&As[(wr + g)     * FAS + ko + t4];
        a[1] = *(const unsigned*)&As[(wr + g + 8) * FAS + ko + t4];
        a[2] = *(const unsigned*)&As[(wr + g)     * FAS + ko + t4 + 4];
        a[3] = *(const unsigned*)&As[(wr + g + 8) * FAS + ko + t4 + 4];
#pragma unroll
        for (int ni = 0; ni < 8; ni++) {
            int n0 = wc + ni * 8;
            unsigned b[2];
            b[0] = *(const unsigned*)&Bb[(kb + t4)     * FBS + n0 + g];
            b[1] = *(const unsigned*)&Bb[(kb + t4 + 4) * FBS + n0 + g];
            mma_f16(acc[ni], a, b);
        }
    }
}

__device__ __forceinline__ void run_stage(const float* __restrict__ W,
                                          const __half2* __restrict__ As, __half2* Bs,
                                          int kp, int nq, int wr, int wc, int g, int t4,
                                          float acc[8][4]) {
    __half2 br[2][4];
    loadB_regs(W, 0, kp, nq, br);
    stsB(Bs, kp, nq, br);
    loadB_regs(W, 32, kp, nq, br);
    __syncthreads();                       // publish buf0 (and caller's As writes)
    int buf = 0;
#pragma unroll
    for (int kt = 0; kt < 8; kt++) {
        if (kt < 7) stsB(Bs + (buf ^ 1) * FB_HALF2, kp, nq, br);
        if (kt < 6) loadB_regs(W, (kt + 2) * 32, kp, nq, br);
        compute_tile(As, Bs + buf * FB_HALF2, kt * 16, wr, wc, g, t4, acc);
        __syncthreads();                   // publish buf^1; guard buf reuse
        buf ^= 1;
    }
}

__global__ void __launch_bounds__(512)
conv_fused(const float* __restrict__ A,
           const float* __restrict__ Wa, const float* __restrict__ ba,
           const float* __restrict__ Wb, const float* __restrict__ bb,
           __half2* __restrict__ out, int M) {
    extern __shared__ __half2 sm[];
    __half2* As = sm;                      // A tile (stage 1), then C1 (stage 2)
    __half2* Bs = sm + FA_HALF2;           // [2][16][FBS]

    int tid = threadIdx.x, lane = tid & 31, w = tid >> 5;
    int wr = (w & 3) * 16;                 // warp row offset   (0/16/32/48)
    int wc = (w >> 2) * 64;                // warp col offset   (0/64/128/192)
    int rowBase = blockIdx.x * FBM;
    int g = lane >> 2, t4 = lane & 3;
    int kp = tid >> 5;                     // B k-pair row 0..15
    int nq = lane * 4;                     // B half2 col base 0..124

    // A tile: fp32 -> half2 smem (one shot)
#pragma unroll
    for (int i = 0; i < 8; i++) {
        int l = tid + 512 * i;
        int r = l >> 6, c4 = l & 63;
        int grow = rowBase + r;
        float4 v = make_float4(0.f, 0.f, 0.f, 0.f);
        if (grow < M) v = *(const float4*)(A + (size_t)grow * HID + c4 * 4);
        As[r * FAS + c4 * 2]     = __floats2half2_rn(v.x, v.y);
        As[r * FAS + c4 * 2 + 1] = __floats2half2_rn(v.z, v.w);
    }

    float acc[8][4];
#pragma unroll
    for (int ni = 0; ni < 8; ni++)
#pragma unroll
        for (int r = 0; r < 4; r++) acc[ni][r] = 0.0f;

    // stage 1: C1 = relu(A @ Wa + ba)
    run_stage(Wa, As, Bs, kp, nq, wr, wc, g, t4, acc);

    // epilogue 1: write C1 (half) back into the A buffer
#pragma unroll
    for (int ni = 0; ni < 8; ni++) {
        int col = wc + ni * 8 + t4 * 2;
        float b0 = ba[col], b1 = ba[col + 1];
        float v00 = fmaxf(acc[ni][0] + b0, 0.f), v01 = fmaxf(acc[ni][1] + b1, 0.f);
        float v10 = fmaxf(acc[ni][2] + b0, 0.f), v11 = fmaxf(acc[ni][3] + b1, 0.f);
        As[(wr + g)     * FAS + (col >> 1)] = __floats2half2_rn(v00, v01);
        As[(wr + g + 8) * FAS + (col >> 1)] = __floats2half2_rn(v10, v11);
        acc[ni][0] = acc[ni][1] = acc[ni][2] = acc[ni][3] = 0.0f;
    }

    // stage 2: out = C1 @ Wb + bb   (run_stage's first sync publishes C1)
    run_stage(Wb, As, Bs, kp, nq, wr, wc, g, t4, acc);

    // epilogue 2: global half2 store
#pragma unroll
    for (int ni = 0; ni < 8; ni++) {
        int col = wc + ni * 8 + t4 * 2;
        float b0 = bb[col], b1 = bb[col + 1];
        int r0 = rowBase + wr + g;
        int r1 = r0 + 8;
        if (r0 < M)
            out[(size_t)r0 * (HID / 2) + (col >> 1)] =
                __floats2half2_rn(acc[ni][0] + b0, acc[ni][1] + b1);
        if (r1 < M)
            out[(size_t)r1 * (HID / 2) + (col >> 1)] =
                __floats2half2_rn(acc[ni][2] + b0, acc[ni][3] + b1);
    }
}

// ------- edge aggregation: warp-per-node float4 gather-max (R7 2-deep) ------
__global__ void agg_kernel() {
    const unsigned FULL = 0xffffffffu;
    int warp = threadIdx.x >> 5;
    int lane = threadIdx.x & 31;
    int n = blockIdx.x * 8 + warp;
    if (n >= N_NODES) return;

    int cnt = min(g_cur[n], ELL_CAP);
    const int* lst = g_ell + n * ELL_CAP;
    const float4* t2v = (const float4*)g_t2h;   // 32 float4 per row

    unsigned ninf = 0xFC00FC00u;
    __half2 mneg = *(__half2*)&ninf;
    __half2 m[8];
#pragma unroll
    for (int q = 0; q < 8; q++) m[q] = mneg;

    for (int base = 0; base < cnt; base += 32) {
        int e = base + lane;
        int idx = (e < cnt) ? lst[e] : 0;
        int c = min(32, cnt - base);
        int j = 0;
        for (; j + 2 <= c; j += 2) {
            int s0 = __shfl_sync(FULL, idx, j);
            int s1 = __shfl_sync(FULL, idx, j + 1);
            float4 v0 = t2v[s0 * 32 + lane];
            float4 v1 = t2v[s1 * 32 + lane];
            m[0] = __hmax2(m[0], *(__half2*)&v0.x);
            m[1] = __hmax2(m[1], *(__half2*)&v0.y);
            m[2] = __hmax2(m[2], *(__half2*)&v0.z);
            m[3] = __hmax2(m[3], *(__half2*)&v0.w);
            m[4] = __hmax2(m[4], *(__half2*)&v1.x);
            m[5] = __hmax2(m[5], *(__half2*)&v1.y);
            m[6] = __hmax2(m[6], *(__half2*)&v1.z);
            m[7] = __hmax2(m[7], *(__half2*)&v1.w);
        }
        if (j < c) {
            int s0 = __shfl_sync(FULL, idx, j);
            float4 v0 = t2v[s0 * 32 + lane];
            m[0] = __hmax2(m[0], *(__half2*)&v0.x);
            m[1] = __hmax2(m[1], *(__half2*)&v0.y);
            m[2] = __hmax2(m[2], *(__half2*)&v0.z);
            m[3] = __hmax2(m[3], *(__half2*)&v0.w);
        }
    }
#pragma unroll
    for (int q = 0; q < 4; q++) m[q] = __hmax2(m[q], m[q + 4]);

    float f[8];
#pragma unroll
    for (int q = 0; q < 4; q++) {
        float2 p = __half22float2(m[q]);
        f[2 * q]     = (cnt > 0) ? p.x : 0.0f;
        f[2 * q + 1] = (cnt > 0) ? p.y : 0.0f;
    }
    float4* hp = (float4*)(g_h + (size_t)n * HID) + lane * 2;
    float4 h0 = hp[0], h1 = hp[1];
    h0.x += silu(f[0]); h0.y += silu(f[1]); h0.z += silu(f[2]); h0.w += silu(f[3]);
    h1.x += silu(f[4]); h1.y += silu(f[5]); h1.z += silu(f[6]); h1.w += silu(f[7]);
    hp[0] = h0; hp[1] = h1;
}

// ------- global mean pool (batch sorted) + re-zero g_cur for next call -----
__global__ void pool_kernel(const int* __restrict__ batch,
                            float* __restrict__ out) {
    int g = blockIdx.x;          // 0..63
    int tid = threadIdx.x;       // 0..255 feature

    int lo = 0, hi = N_NODES;
    while (lo < hi) { int m = (lo + hi) >> 1; if (batch[m] < g) lo = m + 1; else hi = m; }
    int start = lo;
    lo = start; hi = N_NODES;
    while (lo < hi) { int m = (lo + hi) >> 1; if (batch[m] < g + 1) lo = m + 1; else hi = m; }
    int end = lo;

    float s = 0.0f;
    for (int n = start; n < end; n++)
        s += g_h[(size_t)n * HID + tid];
    float c = (float)(end - start);
    out[g * HID + tid] = s / fmaxf(c, 1.0f);

    int z = g * 256 + tid;       // 64*256 = 16384 >= N_NODES
    if (z < N_NODES) g_cur[z] = 0;
}

// ---------------- launch ----------------
extern "C" void kernel_launch(void* const* d_in, const int* in_sizes, int n_in,
                              void* d_out, int out_size) {
    const float* x     = (const float*)d_in[0];
    const int*   ei    = (const int*)d_in[1];
    const int*   batch = (const int*)d_in[2];
    const float* W_emb = (const float*)d_in[3];
    const float* b_emb = (const float*)d_in[4];
    const float* W1a   = (const float*)d_in[5];
    const float* b1a   = (const float*)d_in[6];
    const float* W1b   = (const float*)d_in[7];
    const float* b1b   = (const float*)d_in[8];
    const float* W2a   = (const float*)d_in[9];
    const float* b2a   = (const float*)d_in[10];
    const float* W2b   = (const float*)d_in[11];
    const float* b2b   = (const float*)d_in[12];
    float* out = (float*)d_out;

    const int* src = ei;
    const int* dst = ei + N_EDGES;

    float* h = nullptr; __half2* t2h = nullptr;
    cudaGetSymbolAddress((void**)&h,   g_h);
    cudaGetSymbolAddress((void**)&t2h, g_t2h);

    cudaFuncSetAttribute((const void*)conv_fused,
        cudaFuncAttributeMaxDynamicSharedMemorySize, FUSED_SMEM);

    // setup: ELL fill + embed in one grid (overlapped)
    int embed_blocks = (N_NODES * HID + 255) / 256;
    setup_kernel<<<FILL_BLOCKS + embed_blocks, 256>>>(x, W_emb, b_emb, src, dst);

    int fgrid = (N_NODES + FBM - 1) / FBM;   // 157

    // conv 1 (fused MLP) + aggregation
    conv_fused<<<fgrid, 512, FUSED_SMEM>>>(h, W1a, b1a, W1b, b1b, t2h, N_NODES);
    agg_kernel<<<1250, 256>>>();

    // conv 2
    conv_fused<<<fgrid, 512, FUSED_SMEM>>>(h, W2a, b2a, W2b, b2b, t2h, N_NODES);
    agg_kernel<<<1250, 256>>>();

    // global mean pool (+ g_cur re-zero for next call)
    pool_kernel<<<N_GRAPHS, 256>>>(batch, out);
}

// round 11
// speedup vs baseline: 1.3215x; 1.0021x over previous
#include <cuda_runtime.h>
#include <cuda_fp16.h>
#include <cstdint>
#include <math.h>

#define N_NODES 10000
#define N_EDGES 320000
#define N_GRAPHS 64
#define HID 256
#define ELL_CAP 128
#define FILL_BLOCKS 1250           // 1250*256 = 320000 edges

// ---------------- scratch (static __device__, no allocation) ----------------
__device__ __align__(16) float   g_h  [N_NODES * HID];
__device__ __align__(16) __half2 g_t2h[N_NODES * HID / 2];
__device__ int g_cur[N_NODES];          // zero at module load; re-zeroed by pool tail
__device__ __align__(16) int g_ell[N_NODES * ELL_CAP];

__device__ __forceinline__ float silu(float v) {
    return v / (1.0f + expf(-v));
}

__device__ __forceinline__ int clampi(int v, int hi) {
    return v < 0 ? 0 : (v >= hi ? hi - 1 : v);
}

__device__ __forceinline__ void mma_f16(float* d, const unsigned* a, const unsigned* b) {
    asm volatile(
        "mma.sync.aligned.m16n8k16.row.col.f32.f16.f16.f32 "
        "{%0,%1,%2,%3}, {%4,%5,%6,%7}, {%8,%9}, {%0,%1,%2,%3};"
        : "+f"(d[0]), "+f"(d[1]), "+f"(d[2]), "+f"(d[3])
        : "r"(a[0]), "r"(a[1]), "r"(a[2]), "r"(a[3]),
          "r"(b[0]), "r"(b[1]));
}

// ------- fused setup: ELL fill (blocks [0,FILL_BLOCKS)) + embed (rest) ------
__global__ void setup_kernel(const float* __restrict__ x,
                             const float* __restrict__ w,
                             const float* __restrict__ b,
                             const int* __restrict__ src,
                             const int* __restrict__ dst) {
    int blk = blockIdx.x;
    if (blk < FILL_BLOCKS) {
        int e = blk * 256 + threadIdx.x;
        if (e < N_EDGES) {
            int d = clampi(dst[e], N_NODES);
            int slot = atomicAdd(&g_cur[d], 1);
            if (slot < ELL_CAP)
                g_ell[d * ELL_CAP + slot] = clampi(src[e], N_NODES);
        }
    } else {
        int idx = (blk - FILL_BLOCKS) * 256 + threadIdx.x;
        if (idx < N_NODES * HID) {
            int n = idx >> 8;
            int d = idx & 255;
            g_h[idx] = silu(x[n] * w[d] + b[d]);
        }
    }
}

// ---------------- fused conv: t2h = (relu(h@Wa+ba))@Wb + bb -----------------
// One block: 32 rows x full 256 cols. 256 threads (8 warps; warp = 16x64).
// 2 CTAs/SM for latency hiding. A converted fp32->half once into smem;
// stage-1 result (C1) overwrites the A buffer; W streamed double-buffered.
#define FBM 32
#define FAS 132                    // half2 per A/C1 row (128 + 4)
#define FBS 264                    // half2 per B row (256 + 8 -> frag LDS conflict-free)
#define FA_HALF2 (FBM * FAS)       // 4224
#define FB_HALF2 (16 * FBS)        // 4224 per buffer
#define FUSED_SMEM ((FA_HALF2 + 2 * FB_HALF2) * 4)   // 50688 bytes

// per-thread B tasks (256 threads): rows kp0 = tid>>5 (0..7) and kp1 = kp0+8,
// columns nq = lane*4 within each 128-half2 half of the row.
__device__ __forceinline__ void loadB_regs(const float* __restrict__ W, int k2,
                                           int kp0, int kp1, int nq,
                                           __half2 br[4][4]) {
#pragma unroll
    for (int t = 0; t < 4; t++) {
        int kp = (t < 2) ? kp0 : kp1;
        int n  = nq + (t & 1) * 128;
        float4 v0 = *(const float4*)(W + (size_t)(k2 + 2 * kp)     * HID + n);
        float4 v1 = *(const float4*)(W + (size_t)(k2 + 2 * kp + 1) * HID + n);
        br[t][0] = __floats2half2_rn(v0.x, v1.x);
        br[t][1] = __floats2half2_rn(v0.y, v1.y);
        br[t][2] = __floats2half2_rn(v0.z, v1.z);
        br[t][3] = __floats2half2_rn(v0.w, v1.w);
    }
}

__device__ __forceinline__ void stsB(__half2* Bd, int kp0, int kp1, int nq,
                                     __half2 br[4][4]) {
    *(float4*)&Bd[kp0 * FBS + nq]       = *(float4*)&br[0][0];
    *(float4*)&Bd[kp0 * FBS + nq + 128] = *(float4*)&br[1][0];
    *(float4*)&Bd[kp1 * FBS + nq]       = *(float4*)&br[2][0];
    *(float4*)&Bd[kp1 * FBS + nq + 128] = *(float4*)&br[3][0];
}

__device__ __forceinline__ void compute_tile(const __half2* __restrict__ As,
                                             const __half2* __restrict__ Bb,
                                             int kbase, int wr, int wc, int g, int t4,
                                             float acc[8][4]) {
#pragma unroll
    for (int s = 0; s < 2; s++) {
        int ko = kbase + s * 8;      // half2 offset into full 128-half2 A row
        int kb = s * 8;              // tile-local B row base (k-pair units)
        unsigned a[4];
        a[0] = *(const unsigned*)&As[(wr + g)     * FAS + ko + t4];
        a[1] = *(const unsigned*)&As[(wr + g + 8) * FAS + ko + t4];
        a[2] = *(const unsigned*)&As[(wr + g)     * FAS + ko + t4 + 4];
        a[3] = *(const unsigned*)&As[(wr + g + 8) * FAS + ko + t4 + 4];
#pragma unroll
        for (int ni = 0; ni < 8; ni++) {
            int n0 = wc + ni * 8;
            unsigned b[2];
            b[0] = *(const unsigned*)&Bb[(kb + t4)     * FBS + n0 + g];
            b[1] = *(const unsigned*)&Bb[(kb + t4 + 4) * FBS + n0 + g];
            mma_f16(acc[ni], a, b);
        }
    }
}

__device__ __forceinline__ void run_stage(const float* __restrict__ W,
                                          const __half2* __restrict__ As, __half2* Bs,
                                          int kp0, int kp1, int nq,
                                          int wr, int wc, int g, int t4,
                                          float acc[8][4]) {
    __half2 br[4][4];
    loadB_regs(W, 0, kp0, kp1, nq, br);
    stsB(Bs, kp0, kp1, nq, br);
    loadB_regs(W, 32, kp0, kp1, nq, br);
    __syncthreads();                       // publish buf0 (and caller's As writes)
    int buf = 0;
#pragma unroll
    for (int kt = 0; kt < 8; kt++) {
        if (kt < 7) stsB(Bs + (buf ^ 1) * FB_HALF2, kp0, kp1, nq, br);
        if (kt < 6) loadB_regs(W, (kt + 2) * 32, kp0, kp1, nq, br);
        compute_tile(As, Bs + buf * FB_HALF2, kt * 16, wr, wc, g, t4, acc);
        __syncthreads();                   // publish buf^1; guard buf reuse
        buf ^= 1;
    }
}

__global__ void __launch_bounds__(256, 2)
conv_fused(const float* __restrict__ A,
           const float* __restrict__ Wa, const float* __restrict__ ba,
           const float* __restrict__ Wb, const float* __restrict__ bb,
           __half2* __restrict__ out, int M) {
    extern __shared__ __half2 sm[];
    __half2* As = sm;                      // A tile (stage 1), then C1 (stage 2)
    __half2* Bs = sm + FA_HALF2;           // [2][16][FBS]

    int tid = threadIdx.x, lane = tid & 31, w = tid >> 5;
    int wr = (w & 1) * 16;                 // warp row offset (0/16)
    int wc = (w >> 1) * 64;                // warp col offset (0/64/128/192)
    int rowBase = blockIdx.x * FBM;
    int g = lane >> 2, t4 = lane & 3;
    int kp0 = tid >> 5;                    // B k-pair rows: kp0, kp0+8
    int kp1 = kp0 + 8;
    int nq = lane * 4;                     // B half2 col base 0..124

    // A tile: fp32 -> half2 smem (32 rows x 64 float4 = 2048 float4)
#pragma unroll
    for (int i = 0; i < 8; i++) {
        int l = tid + 256 * i;
        int r = l >> 6, c4 = l & 63;
        int grow = rowBase + r;
        float4 v = make_float4(0.f, 0.f, 0.f, 0.f);
        if (grow < M) v = *(const float4*)(A + (size_t)grow * HID + c4 * 4);
        As[r * FAS + c4 * 2]     = __floats2half2_rn(v.x, v.y);
        As[r * FAS + c4 * 2 + 1] = __floats2half2_rn(v.z, v.w);
    }

    float acc[8][4];
#pragma unroll
    for (int ni = 0; ni < 8; ni++)
#pragma unroll
        for (int r = 0; r < 4; r++) acc[ni][r] = 0.0f;

    // stage 1: C1 = relu(A @ Wa + ba)
    run_stage(Wa, As, Bs, kp0, kp1, nq, wr, wc, g, t4, acc);

    // epilogue 1: write C1 (half) back into the A buffer
#pragma unroll
    for (int ni = 0; ni < 8; ni++) {
        int col = wc + ni * 8 + t4 * 2;
        float b0 = ba[col], b1 = ba[col + 1];
        float v00 = fmaxf(acc[ni][0] + b0, 0.f), v01 = fmaxf(acc[ni][1] + b1, 0.f);
        float v10 = fmaxf(acc[ni][2] + b0, 0.f), v11 = fmaxf(acc[ni][3] + b1, 0.f);
        As[(wr + g)     * FAS + (col >> 1)] = __floats2half2_rn(v00, v01);
        As[(wr + g + 8) * FAS + (col >> 1)] = __floats2half2_rn(v10, v11);
        acc[ni][0] = acc[ni][1] = acc[ni][2] = acc[ni][3] = 0.0f;
    }

    // stage 2: out = C1 @ Wb + bb   (run_stage's first sync publishes C1)
    run_stage(Wb, As, Bs, kp0, kp1, nq, wr, wc, g, t4, acc);

    // epilogue 2: global half2 store
#pragma unroll
    for (int ni = 0; ni < 8; ni++) {
        int col = wc + ni * 8 + t4 * 2;
        float b0 = bb[col], b1 = bb[col + 1];
        int r0 = rowBase + wr + g;
        int r1 = r0 + 8;
        if (r0 < M)
            out[(size_t)r0 * (HID / 2) + (col >> 1)] =
                __floats2half2_rn(acc[ni][0] + b0, acc[ni][1] + b1);
        if (r1 < M)
            out[(size_t)r1 * (HID / 2) + (col >> 1)] =
                __floats2half2_rn(acc[ni][2] + b0, acc[ni][3] + b1);
    }
}

// ------- edge aggregation: warp-per-node float4 gather-max (R7 2-deep) ------
__global__ void agg_kernel() {
    const unsigned FULL = 0xffffffffu;
    int warp = threadIdx.x >> 5;
    int lane = threadIdx.x & 31;
    int n = blockIdx.x * 8 + warp;
    if (n >= N_NODES) return;

    int cnt = min(g_cur[n], ELL_CAP);
    const int* lst = g_ell + n * ELL_CAP;
    const float4* t2v = (const float4*)g_t2h;   // 32 float4 per row

    unsigned ninf = 0xFC00FC00u;
    __half2 mneg = *(__half2*)&ninf;
    __half2 m[8];
#pragma unroll
    for (int q = 0; q < 8; q++) m[q] = mneg;

    for (int base = 0; base < cnt; base += 32) {
        int e = base + lane;
        int idx = (e < cnt) ? lst[e] : 0;
        int c = min(32, cnt - base);
        int j = 0;
        for (; j + 2 <= c; j += 2) {
            int s0 = __shfl_sync(FULL, idx, j);
            int s1 = __shfl_sync(FULL, idx, j + 1);
            float4 v0 = t2v[s0 * 32 + lane];
            float4 v1 = t2v[s1 * 32 + lane];
            m[0] = __hmax2(m[0], *(__half2*)&v0.x);
            m[1] = __hmax2(m[1], *(__half2*)&v0.y);
            m[2] = __hmax2(m[2], *(__half2*)&v0.z);
            m[3] = __hmax2(m[3], *(__half2*)&v0.w);
            m[4] = __hmax2(m[4], *(__half2*)&v1.x);
            m[5] = __hmax2(m[5], *(__half2*)&v1.y);
            m[6] = __hmax2(m[6], *(__half2*)&v1.z);
            m[7] = __hmax2(m[7], *(__half2*)&v1.w);
        }
        if (j < c) {
            int s0 = __shfl_sync(FULL, idx, j);
            float4 v0 = t2v[s0 * 32 + lane];
            m[0] = __hmax2(m[0], *(__half2*)&v0.x);
            m[1] = __hmax2(m[1], *(__half2*)&v0.y);
            m[2] = __hmax2(m[2], *(__half2*)&v0.z);
            m[3] = __hmax2(m[3], *(__half2*)&v0.w);
        }
    }
#pragma unroll
    for (int q = 0; q < 4; q++) m[q] = __hmax2(m[q], m[q + 4]);

    float f[8];
#pragma unroll
    for (int q = 0; q < 4; q++) {
        float2 p = __half22float2(m[q]);
        f[2 * q]     = (cnt > 0) ? p.x : 0.0f;
        f[2 * q + 1] = (cnt > 0) ? p.y : 0.0f;
    }
    float4* hp = (float4*)(g_h + (size_t)n * HID) + lane * 2;
    float4 h0 = hp[0], h1 = hp[1];
    h0.x += silu(f[0]); h0.y += silu(f[1]); h0.z += silu(f[2]); h0.w += silu(f[3]);
    h1.x += silu(f[4]); h1.y += silu(f[5]); h1.z += silu(f[6]); h1.w += silu(f[7]);
    hp[0] = h0; hp[1] = h1;
}

// ------- global mean pool (batch sorted) + re-zero g_cur for next call -----
__global__ void pool_kernel(const int* __restrict__ batch,
                            float* __restrict__ out) {
    int g = blockIdx.x;          // 0..63
    int tid = threadIdx.x;       // 0..255 feature

    int lo = 0, hi = N_NODES;
    while (lo < hi) { int m = (lo + hi) >> 1; if (batch[m] < g) lo = m + 1; else hi = m; }
    int start = lo;
    lo = start; hi = N_NODES;
    while (lo < hi) { int m = (lo + hi) >> 1; if (batch[m] < g + 1) lo = m + 1; else hi = m; }
    int end = lo;

    float s = 0.0f;
    for (int n = start; n < end; n++)
        s += g_h[(size_t)n * HID + tid];
    float c = (float)(end - start);
    out[g * HID + tid] = s / fmaxf(c, 1.0f);

    int z = g * 256 + tid;       // 64*256 = 16384 >= N_NODES
    if (z < N_NODES) g_cur[z] = 0;
}

// ---------------- launch ----------------
extern "C" void kernel_launch(void* const* d_in, const int* in_sizes, int n_in,
                              void* d_out, int out_size) {
    const float* x     = (const float*)d_in[0];
    const int*   ei    = (const int*)d_in[1];
    const int*   batch = (const int*)d_in[2];
    const float* W_emb = (const float*)d_in[3];
    const float* b_emb = (const float*)d_in[4];
    const float* W1a   = (const float*)d_in[5];
    const float* b1a   = (const float*)d_in[6];
    const float* W1b   = (const float*)d_in[7];
    const float* b1b   = (const float*)d_in[8];
    const float* W2a   = (const float*)d_in[9];
    const float* b2a   = (const float*)d_in[10];
    const float* W2b   = (const float*)d_in[11];
    const float* b2b   = (const float*)d_in[12];
    float* out = (float*)d_out;

    const int* src = ei;
    const int* dst = ei + N_EDGES;

    float* h = nullptr; __half2* t2h = nullptr;
    cudaGetSymbolAddress((void**)&h,   g_h);
    cudaGetSymbolAddress((void**)&t2h, g_t2h);

    cudaFuncSetAttribute((const void*)conv_fused,
        cudaFuncAttributeMaxDynamicSharedMemorySize, FUSED_SMEM);

    // setup: ELL fill + embed in one grid (overlapped)
    int embed_blocks = (N_NODES * HID + 255) / 256;
    setup_kernel<<<FILL_BLOCKS + embed_blocks, 256>>>(x, W_emb, b_emb, src, dst);

    int fgrid = (N_NODES + FBM - 1) / FBM;   // 313

    // conv 1 (fused MLP) + aggregation
    conv_fused<<<fgrid, 256, FUSED_SMEM>>>(h, W1a, b1a, W1b, b1b, t2h, N_NODES);
    agg_kernel<<<1250, 256>>>();

    // conv 2
    conv_fused<<<fgrid, 256, FUSED_SMEM>>>(h, W2a, b2a, W2b, b2b, t2h, N_NODES);
    agg_kernel<<<1250, 256>>>();

    // global mean pool (+ g_cur re-zero for next call)
    pool_kernel<<<N_GRAPHS, 256>>>(batch, out);
}

// round 12
// speedup vs baseline: 1.4622x; 1.1065x over previous
#include <cuda_runtime.h>
#include <cuda_fp16.h>
#include <cstdint>
#include <math.h>

#define N_NODES 10000
#define N_EDGES 320000
#define N_GRAPHS 64
#define HID 256
#define ELL_CAP 128
#define FILL_BLOCKS 1250           // 1250*256 = 320000 edges
#define EMBED_BLOCKS 10000         // N_NODES*HID/256
#define PACK_BLOCKS 512            // 4 matrices * 128 blocks

// ---------------- scratch (static __device__, no allocation) ----------------
__device__ __align__(16) float   g_h  [N_NODES * HID];
__device__ __align__(16) __half2 g_t2h[N_NODES * HID / 2];
__device__ __align__(16) __half2 g_wp [4 * 128 * 256];   // packed weights: [m][kp][n]
__device__ int g_cur[N_NODES];          // zero at module load; re-zeroed by pool tail
__device__ __align__(16) int g_ell[N_NODES * ELL_CAP];

__device__ __forceinline__ float silu(float v) {
    return v / (1.0f + expf(-v));
}

__device__ __forceinline__ int clampi(int v, int hi) {
    return v < 0 ? 0 : (v >= hi ? hi - 1 : v);
}

__device__ __forceinline__ void mma_f16(float* d, const unsigned* a, const unsigned* b) {
    asm volatile(
        "mma.sync.aligned.m16n8k16.row.col.f32.f16.f16.f32 "
        "{%0,%1,%2,%3}, {%4,%5,%6,%7}, {%8,%9}, {%0,%1,%2,%3};"
        : "+f"(d[0]), "+f"(d[1]), "+f"(d[2]), "+f"(d[3])
        : "r"(a[0]), "r"(a[1]), "r"(a[2]), "r"(a[3]),
          "r"(b[0]), "r"(b[1]));
}

__device__ __forceinline__ void cp16(void* smem_dst, const void* gsrc) {
    unsigned s = (unsigned)__cvta_generic_to_shared(smem_dst);
    asm volatile("cp.async.ca.shared.global [%0], [%1], 16;"
                 :: "r"(s), "l"(gsrc));
}

// --- fused setup: ELL fill + embed + W pack (one grid, three block ranges) --
__global__ void setup_kernel(const float* __restrict__ x,
                             const float* __restrict__ w,
                             const float* __restrict__ b,
                             const int* __restrict__ src,
                             const int* __restrict__ dst,
                             const float* __restrict__ W1a,
                             const float* __restrict__ W1b,
                             const float* __restrict__ W2a,
                             const float* __restrict__ W2b) {
    int blk = blockIdx.x;
    if (blk < FILL_BLOCKS) {
        int e = blk * 256 + threadIdx.x;
        if (e < N_EDGES) {
            int d = clampi(dst[e], N_NODES);
            int slot = atomicAdd(&g_cur[d], 1);
            if (slot < ELL_CAP)
                g_ell[d * ELL_CAP + slot] = clampi(src[e], N_NODES);
        }
    } else if (blk < FILL_BLOCKS + EMBED_BLOCKS) {
        int idx = (blk - FILL_BLOCKS) * 256 + threadIdx.x;
        if (idx < N_NODES * HID) {
            int n = idx >> 8;
            int d = idx & 255;
            g_h[idx] = silu(x[n] * w[d] + b[d]);
        }
    } else {
        int bl = blk - FILL_BLOCKS - EMBED_BLOCKS;   // 0..511
        int m  = bl >> 7;                             // matrix 0..3
        int idx = (bl & 127) * 256 + threadIdx.x;     // 0..32767
        int kp = idx >> 8;
        int n  = idx & 255;
        const float* Wm = (m == 0) ? W1a : (m == 1) ? W1b : (m == 2) ? W2a : W2b;
        g_wp[m * 32768 + idx] =
            __floats2half2_rn(Wm[(size_t)(2 * kp) * HID + n],
                              Wm[(size_t)(2 * kp + 1) * HID + n]);
    }
}

// ---------------- fused conv: t2h = (relu(h@Wa+ba))@Wb + bb -----------------
// Block: 32 rows x full 256 cols, 256 threads (8 warps; warp = 16x64).
// 3 CTAs/SM. W pre-packed half2 k-pairs; B tiles streamed via cp.async.
#define FBM 32
#define FAS 132                    // half2 per A/C1 row (128 + 4)
#define FBS 264                    // half2 per B row (256 + 8 -> frag LDS conflict-free)
#define FA_HALF2 (FBM * FAS)       // 4224
#define FB_HALF2 (16 * FBS)        // 4224 per buffer
#define FUSED_SMEM ((FA_HALF2 + 2 * FB_HALF2) * 4)   // 50688 bytes

__device__ __forceinline__ void cpB(__half2* dst, const __half2* __restrict__ Wp,
                                    int tid) {
#pragma unroll
    for (int i = 0; i < 4; i++) {
        int l = tid + 256 * i;          // 0..1023
        int r  = l >> 6;                // kp row 0..15
        int c4 = (l & 63) * 4;          // half2 col 0..252
        cp16(&dst[r * FBS + c4], Wp + r * 256 + c4);
    }
}

__device__ __forceinline__ void compute_tile(const __half2* __restrict__ As,
                                             const __half2* __restrict__ Bb,
                                             int kbase, int wr, int wc, int g, int t4,
                                             float acc[8][4]) {
#pragma unroll
    for (int s = 0; s < 2; s++) {
        int ko = kbase + s * 8;      // half2 offset into full 128-half2 A row
        int kb = s * 8;              // tile-local B kp-row base
        unsigned a[4];
        a[0] = *(const unsigned*)&As[(wr + g)     * FAS + ko + t4];
        a[1] = *(const unsigned*)&As[(wr + g + 8) * FAS + ko + t4];
        a[2] = *(const unsigned*)&As[(wr + g)     * FAS + ko + t4 + 4];
        a[3] = *(const unsigned*)&As[(wr + g + 8) * FAS + ko + t4 + 4];
#pragma unroll
        for (int ni = 0; ni < 8; ni++) {
            int n0 = wc + ni * 8;
            unsigned b[2];
            b[0] = *(const unsigned*)&Bb[(kb + t4)     * FBS + n0 + g];
            b[1] = *(const unsigned*)&Bb[(kb + t4 + 4) * FBS + n0 + g];
            mma_f16(acc[ni], a, b);
        }
    }
}

__device__ __forceinline__ void run_stage(const __half2* __restrict__ Wp,
                                          const __half2* __restrict__ As, __half2* Bs,
                                          int tid, int wr, int wc, int g, int t4,
                                          float acc[8][4]) {
    cpB(Bs, Wp, tid);
    asm volatile("cp.async.commit_group;");
    int buf = 0;
#pragma unroll
    for (int kt = 0; kt < 8; kt++) {
        if (kt < 7) {
            cpB(Bs + (buf ^ 1) * FB_HALF2, Wp + (kt + 1) * 4096, tid);
            asm volatile("cp.async.commit_group;");
            asm volatile("cp.async.wait_group 1;");   // tile kt landed
        } else {
            asm volatile("cp.async.wait_group 0;");
        }
        __syncthreads();                 // publish tile kt (and As on kt==0)
        compute_tile(As, Bs + buf * FB_HALF2, kt * 16, wr, wc, g, t4, acc);
        __syncthreads();                 // all reads of buf done before overwrite
        buf ^= 1;
    }
}

__global__ void __launch_bounds__(256, 3)
conv_fused(const float* __restrict__ A,
           const __half2* __restrict__ Wap, const float* __restrict__ ba,
           const __half2* __restrict__ Wbp, const float* __restrict__ bb,
           __half2* __restrict__ out, int M) {
    extern __shared__ __half2 sm[];
    __half2* As = sm;                      // A tile (stage 1), then C1 (stage 2)
    __half2* Bs = sm + FA_HALF2;           // [2][16][FBS]

    int tid = threadIdx.x, lane = tid & 31, w = tid >> 5;
    int wr = (w & 1) * 16;                 // warp row offset (0/16)
    int wc = (w >> 1) * 64;                // warp col offset (0/64/128/192)
    int rowBase = blockIdx.x * FBM;
    int g = lane >> 2, t4 = lane & 3;

    // A tile: fp32 -> half2 smem (32 rows x 64 float4)
#pragma unroll
    for (int i = 0; i < 8; i++) {
        int l = tid + 256 * i;
        int r = l >> 6, c4 = l & 63;
        int grow = rowBase + r;
        float4 v = make_float4(0.f, 0.f, 0.f, 0.f);
        if (grow < M) v = *(const float4*)(A + (size_t)grow * HID + c4 * 4);
        As[r * FAS + c4 * 2]     = __floats2half2_rn(v.x, v.y);
        As[r * FAS + c4 * 2 + 1] = __floats2half2_rn(v.z, v.w);
    }

    float acc[8][4];
#pragma unroll
    for (int ni = 0; ni < 8; ni++)
#pragma unroll
        for (int r = 0; r < 4; r++) acc[ni][r] = 0.0f;

    // stage 1: C1 = relu(A @ Wa + ba)
    run_stage(Wap, As, Bs, tid, wr, wc, g, t4, acc);

    // epilogue 1: write C1 (half) back into the A buffer
#pragma unroll
    for (int ni = 0; ni < 8; ni++) {
        int col = wc + ni * 8 + t4 * 2;
        float b0 = ba[col], b1 = ba[col + 1];
        float v00 = fmaxf(acc[ni][0] + b0, 0.f), v01 = fmaxf(acc[ni][1] + b1, 0.f);
        float v10 = fmaxf(acc[ni][2] + b0, 0.f), v11 = fmaxf(acc[ni][3] + b1, 0.f);
        As[(wr + g)     * FAS + (col >> 1)] = __floats2half2_rn(v00, v01);
        As[(wr + g + 8) * FAS + (col >> 1)] = __floats2half2_rn(v10, v11);
        acc[ni][0] = acc[ni][1] = acc[ni][2] = acc[ni][3] = 0.0f;
    }

    // stage 2: out = C1 @ Wb + bb   (run_stage's first sync publishes C1)
    run_stage(Wbp, As, Bs, tid, wr, wc, g, t4, acc);

    // epilogue 2: global half2 store
#pragma unroll
    for (int ni = 0; ni < 8; ni++) {
        int col = wc + ni * 8 + t4 * 2;
        float b0 = bb[col], b1 = bb[col + 1];
        int r0 = rowBase + wr + g;
        int r1 = r0 + 8;
        if (r0 < M)
            out[(size_t)r0 * (HID / 2) + (col >> 1)] =
                __floats2half2_rn(acc[ni][0] + b0, acc[ni][1] + b1);
        if (r1 < M)
            out[(size_t)r1 * (HID / 2) + (col >> 1)] =
                __floats2half2_rn(acc[ni][2] + b0, acc[ni][3] + b1);
    }
}

// ------- edge aggregation: warp-per-node float4 gather-max (R7 2-deep) ------
__global__ void agg_kernel() {
    const unsigned FULL = 0xffffffffu;
    int warp = threadIdx.x >> 5;
    int lane = threadIdx.x & 31;
    int n = blockIdx.x * 8 + warp;
    if (n >= N_NODES) return;

    int cnt = min(g_cur[n], ELL_CAP);
    const int* lst = g_ell + n * ELL_CAP;
    const float4* t2v = (const float4*)g_t2h;   // 32 float4 per row

    unsigned ninf = 0xFC00FC00u;
    __half2 mneg = *(__half2*)&ninf;
    __half2 m[8];
#pragma unroll
    for (int q = 0; q < 8; q++) m[q] = mneg;

    for (int base = 0; base < cnt; base += 32) {
        int e = base + lane;
        int idx = (e < cnt) ? lst[e] : 0;
        int c = min(32, cnt - base);
        int j = 0;
        for (; j + 2 <= c; j += 2) {
            int s0 = __shfl_sync(FULL, idx, j);
            int s1 = __shfl_sync(FULL, idx, j + 1);
            float4 v0 = t2v[s0 * 32 + lane];
            float4 v1 = t2v[s1 * 32 + lane];
            m[0] = __hmax2(m[0], *(__half2*)&v0.x);
            m[1] = __hmax2(m[1], *(__half2*)&v0.y);
            m[2] = __hmax2(m[2], *(__half2*)&v0.z);
            m[3] = __hmax2(m[3], *(__half2*)&v0.w);
            m[4] = __hmax2(m[4], *(__half2*)&v1.x);
            m[5] = __hmax2(m[5], *(__half2*)&v1.y);
            m[6] = __hmax2(m[6], *(__half2*)&v1.z);
            m[7] = __hmax2(m[7], *(__half2*)&v1.w);
        }
        if (j < c) {
            int s0 = __shfl_sync(FULL, idx, j);
            float4 v0 = t2v[s0 * 32 + lane];
            m[0] = __hmax2(m[0], *(__half2*)&v0.x);
            m[1] = __hmax2(m[1], *(__half2*)&v0.y);
            m[2] = __hmax2(m[2], *(__half2*)&v0.z);
            m[3] = __hmax2(m[3], *(__half2*)&v0.w);
        }
    }
#pragma unroll
    for (int q = 0; q < 4; q++) m[q] = __hmax2(m[q], m[q + 4]);

    float f[8];
#pragma unroll
    for (int q = 0; q < 4; q++) {
        float2 p = __half22float2(m[q]);
        f[2 * q]     = (cnt > 0) ? p.x : 0.0f;
        f[2 * q + 1] = (cnt > 0) ? p.y : 0.0f;
    }
    float4* hp = (float4*)(g_h + (size_t)n * HID) + lane * 2;
    float4 h0 = hp[0], h1 = hp[1];
    h0.x += silu(f[0]); h0.y += silu(f[1]); h0.z += silu(f[2]); h0.w += silu(f[3]);
    h1.x += silu(f[4]); h1.y += silu(f[5]); h1.z += silu(f[6]); h1.w += silu(f[7]);
    hp[0] = h0; hp[1] = h1;
}

// ------- global mean pool (batch sorted) + re-zero g_cur for next call -----
__global__ void pool_kernel(const int* __restrict__ batch,
                            float* __restrict__ out) {
    int g = blockIdx.x;          // 0..63
    int tid = threadIdx.x;       // 0..255 feature

    int lo = 0, hi = N_NODES;
    while (lo < hi) { int m = (lo + hi) >> 1; if (batch[m] < g) lo = m + 1; else hi = m; }
    int start = lo;
    lo = start; hi = N_NODES;
    while (lo < hi) { int m = (lo + hi) >> 1; if (batch[m] < g + 1) lo = m + 1; else hi = m; }
    int end = lo;

    float s = 0.0f;
    for (int n = start; n < end; n++)
        s += g_h[(size_t)n * HID + tid];
    float c = (float)(end - start);
    out[g * HID + tid] = s / fmaxf(c, 1.0f);

    int z = g * 256 + tid;       // 64*256 = 16384 >= N_NODES
    if (z < N_NODES) g_cur[z] = 0;
}

// ---------------- launch ----------------
extern "C" void kernel_launch(void* const* d_in, const int* in_sizes, int n_in,
                              void* d_out, int out_size) {
    const float* x     = (const float*)d_in[0];
    const int*   ei    = (const int*)d_in[1];
    const int*   batch = (const int*)d_in[2];
    const float* W_emb = (const float*)d_in[3];
    const float* b_emb = (const float*)d_in[4];
    const float* W1a   = (const float*)d_in[5];
    const float* b1a   = (const float*)d_in[6];
    const float* W1b   = (const float*)d_in[7];
    const float* b1b   = (const float*)d_in[8];
    const float* W2a   = (const float*)d_in[9];
    const float* b2a   = (const float*)d_in[10];
    const float* W2b   = (const float*)d_in[11];
    const float* b2b   = (const float*)d_in[12];
    float* out = (float*)d_out;

    const int* src = ei;
    const int* dst = ei + N_EDGES;

    float* h = nullptr; __half2* t2h = nullptr; __half2* wp = nullptr;
    cudaGetSymbolAddress((void**)&h,   g_h);
    cudaGetSymbolAddress((void**)&t2h, g_t2h);
    cudaGetSymbolAddress((void**)&wp,  g_wp);

    cudaFuncSetAttribute((const void*)conv_fused,
        cudaFuncAttributeMaxDynamicSharedMemorySize, FUSED_SMEM);

    // setup: ELL fill + embed + W pack in one grid
    setup_kernel<<<FILL_BLOCKS + EMBED_BLOCKS + PACK_BLOCKS, 256>>>(
        x, W_emb, b_emb, src, dst, W1a, W1b, W2a, W2b);

    int fgrid = (N_NODES + FBM - 1) / FBM;   // 313

    // conv 1 (fused MLP) + aggregation
    conv_fused<<<fgrid, 256, FUSED_SMEM>>>(h, wp, b1a, wp + 32768, b1b, t2h, N_NODES);
    agg_kernel<<<1250, 256>>>();

    // conv 2
    conv_fused<<<fgrid, 256, FUSED_SMEM>>>(h, wp + 65536, b2a, wp + 98304, b2b, t2h, N_NODES);
    agg_kernel<<<1250, 256>>>();

    // global mean pool (+ g_cur re-zero for next call)
    pool_kernel<<<N_GRAPHS, 256>>>(batch, out);
}

// round 13
// speedup vs baseline: 1.5225x; 1.0412x over previous
#include <cuda_runtime.h>
#include <cuda_fp16.h>
#include <cstdint>
#include <math.h>

#define N_NODES 10000
#define N_EDGES 320000
#define N_GRAPHS 64
#define HID 256
#define ELL_CAP 128
#define FILL_BLOCKS 1250           // 1250*256 = 320000 edges
#define EMBED_BLOCKS 10000         // N_NODES*HID/256
#define PACK_BLOCKS 512            // 4 matrices * 128 blocks

// ---------------- scratch (static __device__, no allocation) ----------------
__device__ __align__(16) float   g_h  [N_NODES * HID];
__device__ __align__(16) __half2 g_t2h[N_NODES * HID / 2];
__device__ __align__(16) __half2 g_wp [4 * 128 * 256];   // packed weights: [m][kp][n]
__device__ int g_cur[N_NODES];          // zero at module load; re-zeroed by pool tail
__device__ __align__(16) int g_ell[N_NODES * ELL_CAP];

__device__ __forceinline__ float silu(float v) {
    return v / (1.0f + expf(-v));
}

__device__ __forceinline__ int clampi(int v, int hi) {
    return v < 0 ? 0 : (v >= hi ? hi - 1 : v);
}

__device__ __forceinline__ void mma_f16(float* d, const unsigned* a, const unsigned* b) {
    asm volatile(
        "mma.sync.aligned.m16n8k16.row.col.f32.f16.f16.f32 "
        "{%0,%1,%2,%3}, {%4,%5,%6,%7}, {%8,%9}, {%0,%1,%2,%3};"
        : "+f"(d[0]), "+f"(d[1]), "+f"(d[2]), "+f"(d[3])
        : "r"(a[0]), "r"(a[1]), "r"(a[2]), "r"(a[3]),
          "r"(b[0]), "r"(b[1]));
}

__device__ __forceinline__ void cp16(void* smem_dst, const void* gsrc) {
    unsigned s = (unsigned)__cvta_generic_to_shared(smem_dst);
    asm volatile("cp.async.ca.shared.global [%0], [%1], 16;"
                 :: "r"(s), "l"(gsrc));
}

// --- fused setup: ELL fill + embed + W pack (one grid, three block ranges) --
__global__ void setup_kernel(const float* __restrict__ x,
                             const float* __restrict__ w,
                             const float* __restrict__ b,
                             const int* __restrict__ src,
                             const int* __restrict__ dst,
                             const float* __restrict__ W1a,
                             const float* __restrict__ W1b,
                             const float* __restrict__ W2a,
                             const float* __restrict__ W2b) {
    int blk = blockIdx.x;
    if (blk < FILL_BLOCKS) {
        int e = blk * 256 + threadIdx.x;
        if (e < N_EDGES) {
            int d = clampi(dst[e], N_NODES);
            int slot = atomicAdd(&g_cur[d], 1);
            if (slot < ELL_CAP)
                g_ell[d * ELL_CAP + slot] = clampi(src[e], N_NODES);
        }
    } else if (blk < FILL_BLOCKS + EMBED_BLOCKS) {
        int idx = (blk - FILL_BLOCKS) * 256 + threadIdx.x;
        if (idx < N_NODES * HID) {
            int n = idx >> 8;
            int d = idx & 255;
            g_h[idx] = silu(x[n] * w[d] + b[d]);
        }
    } else {
        int bl = blk - FILL_BLOCKS - EMBED_BLOCKS;   // 0..511
        int m  = bl >> 7;                             // matrix 0..3
        int idx = (bl & 127) * 256 + threadIdx.x;     // 0..32767
        int kp = idx >> 8;
        int n  = idx & 255;
        const float* Wm = (m == 0) ? W1a : (m == 1) ? W1b : (m == 2) ? W2a : W2b;
        g_wp[m * 32768 + idx] =
            __floats2half2_rn(Wm[(size_t)(2 * kp) * HID + n],
                              Wm[(size_t)(2 * kp + 1) * HID + n]);
    }
}

// ---------------- fused conv: t2h = (relu(h@Wa+ba))@Wb + bb -----------------
// Block: 64 rows x full 256 cols, 256 threads (8 warps; warp = 32x64, 2 mi).
// 2 CTAs/SM, single wave (157 blocks / 296 slots). B tiles via cp.async from
// pre-packed half2 weights; B fragments reused across 2 M-subtiles.
#define FBM 64
#define FAS 132                    // half2 per A/C1 row (128 + 4)
#define FBS 264                    // half2 per B row (256 + 8 -> frag LDS conflict-free)
#define FA_HALF2 (FBM * FAS)       // 8448
#define FB_HALF2 (16 * FBS)        // 4224 per buffer
#define FUSED_SMEM ((FA_HALF2 + 2 * FB_HALF2) * 4)   // 67584 bytes

__device__ __forceinline__ void cpB(__half2* dst, const __half2* __restrict__ Wp,
                                    int tid) {
#pragma unroll
    for (int i = 0; i < 4; i++) {
        int l = tid + 256 * i;          // 0..1023
        int r  = l >> 6;                // kp row 0..15
        int c4 = (l & 63) * 4;          // half2 col 0..252
        cp16(&dst[r * FBS + c4], Wp + r * 256 + c4);
    }
}

__device__ __forceinline__ void compute_tile(const __half2* __restrict__ As,
                                             const __half2* __restrict__ Bb,
                                             int kbase, int wr, int wc, int g, int t4,
                                             float acc[2][8][4]) {
#pragma unroll
    for (int s = 0; s < 2; s++) {
        int ko = kbase + s * 8;      // half2 offset into full 128-half2 A row
        int kb = s * 8;              // tile-local B kp-row base
        unsigned a[2][4];
#pragma unroll
        for (int mi = 0; mi < 2; mi++) {
            int m0 = wr + mi * 16;
            a[mi][0] = *(const unsigned*)&As[(m0 + g)     * FAS + ko + t4];
            a[mi][1] = *(const unsigned*)&As[(m0 + g + 8) * FAS + ko + t4];
            a[mi][2] = *(const unsigned*)&As[(m0 + g)     * FAS + ko + t4 + 4];
            a[mi][3] = *(const unsigned*)&As[(m0 + g + 8) * FAS + ko + t4 + 4];
        }
#pragma unroll
        for (int ni = 0; ni < 8; ni++) {
            int n0 = wc + ni * 8;
            unsigned b[2];
            b[0] = *(const unsigned*)&Bb[(kb + t4)     * FBS + n0 + g];
            b[1] = *(const unsigned*)&Bb[(kb + t4 + 4) * FBS + n0 + g];
            mma_f16(acc[0][ni], a[0], b);
            mma_f16(acc[1][ni], a[1], b);
        }
    }
}

__device__ __forceinline__ void run_stage(const __half2* __restrict__ Wp,
                                          const __half2* __restrict__ As, __half2* Bs,
                                          int tid, int wr, int wc, int g, int t4,
                                          float acc[2][8][4]) {
    cpB(Bs, Wp, tid);
    asm volatile("cp.async.commit_group;");
    int buf = 0;
#pragma unroll
    for (int kt = 0; kt < 8; kt++) {
        if (kt < 7) {
            cpB(Bs + (buf ^ 1) * FB_HALF2, Wp + (kt + 1) * 4096, tid);
            asm volatile("cp.async.commit_group;");
            asm volatile("cp.async.wait_group 1;");   // tile kt landed
        } else {
            asm volatile("cp.async.wait_group 0;");
        }
        __syncthreads();                 // publish tile kt (and As on kt==0)
        compute_tile(As, Bs + buf * FB_HALF2, kt * 16, wr, wc, g, t4, acc);
        __syncthreads();                 // all reads of buf done before overwrite
        buf ^= 1;
    }
}

__global__ void __launch_bounds__(256, 2)
conv_fused(const float* __restrict__ A,
           const __half2* __restrict__ Wap, const float* __restrict__ ba,
           const __half2* __restrict__ Wbp, const float* __restrict__ bb,
           __half2* __restrict__ out, int M) {
    extern __shared__ __half2 sm[];
    __half2* As = sm;                      // A tile (stage 1), then C1 (stage 2)
    __half2* Bs = sm + FA_HALF2;           // [2][16][FBS]

    int tid = threadIdx.x, lane = tid & 31, w = tid >> 5;
    int wr = (w & 1) * 32;                 // warp row offset (0/32)
    int wc = (w >> 1) * 64;                // warp col offset (0/64/128/192)
    int rowBase = blockIdx.x * FBM;
    int g = lane >> 2, t4 = lane & 3;

    // A tile: fp32 -> half2 smem (64 rows x 64 float4 = 4096 float4)
#pragma unroll
    for (int i = 0; i < 16; i++) {
        int l = tid + 256 * i;
        int r = l >> 6, c4 = l & 63;
        int grow = rowBase + r;
        float4 v = make_float4(0.f, 0.f, 0.f, 0.f);
        if (grow < M) v = *(const float4*)(A + (size_t)grow * HID + c4 * 4);
        As[r * FAS + c4 * 2]     = __floats2half2_rn(v.x, v.y);
        As[r * FAS + c4 * 2 + 1] = __floats2half2_rn(v.z, v.w);
    }

    float acc[2][8][4];
#pragma unroll
    for (int mi = 0; mi < 2; mi++)
#pragma unroll
        for (int ni = 0; ni < 8; ni++)
#pragma unroll
            for (int r = 0; r < 4; r++) acc[mi][ni][r] = 0.0f;

    // stage 1: C1 = relu(A @ Wa + ba)
    run_stage(Wap, As, Bs, tid, wr, wc, g, t4, acc);

    // epilogue 1: write C1 (half) back into the A buffer
#pragma unroll
    for (int mi = 0; mi < 2; mi++)
#pragma unroll
        for (int ni = 0; ni < 8; ni++) {
            int col = wc + ni * 8 + t4 * 2;
            float b0 = ba[col], b1 = ba[col + 1];
            float v00 = fmaxf(acc[mi][ni][0] + b0, 0.f), v01 = fmaxf(acc[mi][ni][1] + b1, 0.f);
            float v10 = fmaxf(acc[mi][ni][2] + b0, 0.f), v11 = fmaxf(acc[mi][ni][3] + b1, 0.f);
            int r0 = wr + mi * 16 + g;
            As[r0       * FAS + (col >> 1)] = __floats2half2_rn(v00, v01);
            As[(r0 + 8) * FAS + (col >> 1)] = __floats2half2_rn(v10, v11);
            acc[mi][ni][0] = acc[mi][ni][1] = acc[mi][ni][2] = acc[mi][ni][3] = 0.0f;
        }

    // stage 2: out = C1 @ Wb + bb   (run_stage's first sync publishes C1)
    run_stage(Wbp, As, Bs, tid, wr, wc, g, t4, acc);

    // epilogue 2: global half2 store
#pragma unroll
    for (int mi = 0; mi < 2; mi++)
#pragma unroll
        for (int ni = 0; ni < 8; ni++) {
            int col = wc + ni * 8 + t4 * 2;
            float b0 = bb[col], b1 = bb[col + 1];
            int r0 = rowBase + wr + mi * 16 + g;
            int r1 = r0 + 8;
            if (r0 < M)
                out[(size_t)r0 * (HID / 2) + (col >> 1)] =
                    __floats2half2_rn(acc[mi][ni][0] + b0, acc[mi][ni][1] + b1);
            if (r1 < M)
                out[(size_t)r1 * (HID / 2) + (col >> 1)] =
                    __floats2half2_rn(acc[mi][ni][2] + b0, acc[mi][ni][3] + b1);
        }
}

// ------- edge aggregation: warp-per-node float4 gather-max (R7 2-deep) ------
__global__ void agg_kernel() {
    const unsigned FULL = 0xffffffffu;
    int warp = threadIdx.x >> 5;
    int lane = threadIdx.x & 31;
    int n = blockIdx.x * 8 + warp;
    if (n >= N_NODES) return;

    int cnt = min(g_cur[n], ELL_CAP);
    const int* lst = g_ell + n * ELL_CAP;
    const float4* t2v = (const float4*)g_t2h;   // 32 float4 per row

    unsigned ninf = 0xFC00FC00u;
    __half2 mneg = *(__half2*)&ninf;
    __half2 m[8];
#pragma unroll
    for (int q = 0; q < 8; q++) m[q] = mneg;

    for (int base = 0; base < cnt; base += 32) {
        int e = base + lane;
        int idx = (e < cnt) ? lst[e] : 0;
        int c = min(32, cnt - base);
        int j = 0;
        for (; j + 2 <= c; j += 2) {
            int s0 = __shfl_sync(FULL, idx, j);
            int s1 = __shfl_sync(FULL, idx, j + 1);
            float4 v0 = t2v[s0 * 32 + lane];
            float4 v1 = t2v[s1 * 32 + lane];
            m[0] = __hmax2(m[0], *(__half2*)&v0.x);
            m[1] = __hmax2(m[1], *(__half2*)&v0.y);
            m[2] = __hmax2(m[2], *(__half2*)&v0.z);
            m[3] = __hmax2(m[3], *(__half2*)&v0.w);
            m[4] = __hmax2(m[4], *(__half2*)&v1.x);
            m[5] = __hmax2(m[5], *(__half2*)&v1.y);
            m[6] = __hmax2(m[6], *(__half2*)&v1.z);
            m[7] = __hmax2(m[7], *(__half2*)&v1.w);
        }
        if (j < c) {
            int s0 = __shfl_sync(FULL, idx, j);
            float4 v0 = t2v[s0 * 32 + lane];
            m[0] = __hmax2(m[0], *(__half2*)&v0.x);
            m[1] = __hmax2(m[1], *(__half2*)&v0.y);
            m[2] = __hmax2(m[2], *(__half2*)&v0.z);
            m[3] = __hmax2(m[3], *(__half2*)&v0.w);
        }
    }
#pragma unroll
    for (int q = 0; q < 4; q++) m[q] = __hmax2(m[q], m[q + 4]);

    float f[8];
#pragma unroll
    for (int q = 0; q < 4; q++) {
        float2 p = __half22float2(m[q]);
        f[2 * q]     = (cnt > 0) ? p.x : 0.0f;
        f[2 * q + 1] = (cnt > 0) ? p.y : 0.0f;
    }
    float4* hp = (float4*)(g_h + (size_t)n * HID) + lane * 2;
    float4 h0 = hp[0], h1 = hp[1];
    h0.x += silu(f[0]); h0.y += silu(f[1]); h0.z += silu(f[2]); h0.w += silu(f[3]);
    h1.x += silu(f[4]); h1.y += silu(f[5]); h1.z += silu(f[6]); h1.w += silu(f[7]);
    hp[0] = h0; hp[1] = h1;
}

// ------- global mean pool (batch sorted) + re-zero g_cur for next call -----
__global__ void pool_kernel(const int* __restrict__ batch,
                            float* __restrict__ out) {
    int g = blockIdx.x;          // 0..63
    int tid = threadIdx.x;       // 0..255 feature

    int lo = 0, hi = N_NODES;
    while (lo < hi) { int m = (lo + hi) >> 1; if (batch[m] < g) lo = m + 1; else hi = m; }
    int start = lo;
    lo = start; hi = N_NODES;
    while (lo < hi) { int m = (lo + hi) >> 1; if (batch[m] < g + 1) lo = m + 1; else hi = m; }
    int end = lo;

    float s = 0.0f;
    for (int n = start; n < end; n++)
        s += g_h[(size_t)n * HID + tid];
    float c = (float)(end - start);
    out[g * HID + tid] = s / fmaxf(c, 1.0f);

    int z = g * 256 + tid;       // 64*256 = 16384 >= N_NODES
    if (z < N_NODES) g_cur[z] = 0;
}

// ---------------- launch ----------------
extern "C" void kernel_launch(void* const* d_in, const int* in_sizes, int n_in,
                              void* d_out, int out_size) {
    const float* x     = (const float*)d_in[0];
    const int*   ei    = (const int*)d_in[1];
    const int*   batch = (const int*)d_in[2];
    const float* W_emb = (const float*)d_in[3];
    const float* b_emb = (const float*)d_in[4];
    const float* W1a   = (const float*)d_in[5];
    const float* b1a   = (const float*)d_in[6];
    const float* W1b   = (const float*)d_in[7];
    const float* b1b   = (const float*)d_in[8];
    const float* W2a   = (const float*)d_in[9];
    const float* b2a   = (const float*)d_in[10];
    const float* W2b   = (const float*)d_in[11];
    const float* b2b   = (const float*)d_in[12];
    float* out = (float*)d_out;

    const int* src = ei;
    const int* dst = ei + N_EDGES;

    float* h = nullptr; __half2* t2h = nullptr; __half2* wp = nullptr;
    cudaGetSymbolAddress((void**)&h,   g_h);
    cudaGetSymbolAddress((void**)&t2h, g_t2h);
    cudaGetSymbolAddress((void**)&wp,  g_wp);

    cudaFuncSetAttribute((const void*)conv_fused,
        cudaFuncAttributeMaxDynamicSharedMemorySize, FUSED_SMEM);

    // setup: ELL fill + embed + W pack in one grid
    setup_kernel<<<FILL_BLOCKS + EMBED_BLOCKS + PACK_BLOCKS, 256>>>(
        x, W_emb, b_emb, src, dst, W1a, W1b, W2a, W2b);

    int fgrid = (N_NODES + FBM - 1) / FBM;   // 157

    // conv 1 (fused MLP) + aggregation
    conv_fused<<<fgrid, 256, FUSED_SMEM>>>(h, wp, b1a, wp + 32768, b1b, t2h, N_NODES);
    agg_kernel<<<1250, 256>>>();

    // conv 2
    conv_fused<<<fgrid, 256, FUSED_SMEM>>>(h, wp + 65536, b2a, wp + 98304, b2b, t2h, N_NODES);
    agg_kernel<<<1250, 256>>>();

    // global mean pool (+ g_cur re-zero for next call)
    pool_kernel<<<N_GRAPHS, 256>>>(batch, out);
}

// round 14
// speedup vs baseline: 1.6217x; 1.0652x over previous
#include <cuda_runtime.h>
#include <cuda_fp16.h>
#include <cstdint>
#include <math.h>

#define N_NODES 10000
#define N_EDGES 320000
#define N_GRAPHS 64
#define HID 256
#define ELL_CAP 128
#define FILL_BLOCKS 1250           // 1250*256 = 320000 edges
#define EMBED_BLOCKS 10000         // N_NODES*HID/256
#define PACK_BLOCKS 256            // 4 matrices * 65536 halves / (256 thr * 4)

// ---------------- scratch (static __device__, no allocation) ----------------
__device__ __align__(16) float   g_h  [N_NODES * HID];
__device__ __align__(16) __half2 g_t2h[N_NODES * HID / 2];
__device__ __align__(16) __half  g_wph[4 * 256 * 256];   // fp16 weights, k-major [m][k][n]
__device__ int g_cur[N_NODES];          // zero at module load; re-zeroed by pool tail
__device__ __align__(16) int g_ell[N_NODES * ELL_CAP];

__device__ __forceinline__ float silu(float v) {
    return v / (1.0f + expf(-v));
}

__device__ __forceinline__ int clampi(int v, int hi) {
    return v < 0 ? 0 : (v >= hi ? hi - 1 : v);
}

__device__ __forceinline__ void mma_f16(float* d, const unsigned* a, const unsigned* b) {
    asm volatile(
        "mma.sync.aligned.m16n8k16.row.col.f32.f16.f16.f32 "
        "{%0,%1,%2,%3}, {%4,%5,%6,%7}, {%8,%9}, {%0,%1,%2,%3};"
        : "+f"(d[0]), "+f"(d[1]), "+f"(d[2]), "+f"(d[3])
        : "r"(a[0]), "r"(a[1]), "r"(a[2]), "r"(a[3]),
          "r"(b[0]), "r"(b[1]));
}

__device__ __forceinline__ void ldsm_x4(unsigned* r, uint32_t addr) {
    asm volatile("ldmatrix.sync.aligned.m8n8.x4.shared.b16 {%0,%1,%2,%3}, [%4];"
                 : "=r"(r[0]), "=r"(r[1]), "=r"(r[2]), "=r"(r[3]) : "r"(addr));
}

__device__ __forceinline__ void ldsm_x4_trans(unsigned* r, uint32_t addr) {
    asm volatile("ldmatrix.sync.aligned.m8n8.x4.trans.shared.b16 {%0,%1,%2,%3}, [%4];"
                 : "=r"(r[0]), "=r"(r[1]), "=r"(r[2]), "=r"(r[3]) : "r"(addr));
}

__device__ __forceinline__ void cp16(void* smem_dst, const void* gsrc) {
    unsigned s = (unsigned)__cvta_generic_to_shared(smem_dst);
    asm volatile("cp.async.ca.shared.global [%0], [%1], 16;"
                 :: "r"(s), "l"(gsrc));
}

// --- fused setup: ELL fill + embed + W half-pack (one grid, three ranges) ---
__global__ void setup_kernel(const float* __restrict__ x,
                             const float* __restrict__ w,
                             const float* __restrict__ b,
                             const int* __restrict__ src,
                             const int* __restrict__ dst,
                             const float* __restrict__ W1a,
                             const float* __restrict__ W1b,
                             const float* __restrict__ W2a,
                             const float* __restrict__ W2b) {
    int blk = blockIdx.x;
    if (blk < FILL_BLOCKS) {
        int e = blk * 256 + threadIdx.x;
        if (e < N_EDGES) {
            int d = clampi(dst[e], N_NODES);
            int slot = atomicAdd(&g_cur[d], 1);
            if (slot < ELL_CAP)
                g_ell[d * ELL_CAP + slot] = clampi(src[e], N_NODES);
        }
    } else if (blk < FILL_BLOCKS + EMBED_BLOCKS) {
        int idx = (blk - FILL_BLOCKS) * 256 + threadIdx.x;
        if (idx < N_NODES * HID) {
            int n = idx >> 8;
            int d = idx & 255;
            g_h[idx] = silu(x[n] * w[d] + b[d]);
        }
    } else {
        int t = (blk - FILL_BLOCKS - EMBED_BLOCKS) * 256 + threadIdx.x;  // 0..65535
        int m   = t >> 14;                 // matrix 0..3
        int off = (t & 16383) * 4;         // element offset (W is [k][n] row-major)
        const float* Wm = (m == 0) ? W1a : (m == 1) ? W1b : (m == 2) ? W2a : W2b;
        float4 v = *(const float4*)(Wm + off);
        __half2* d2 = (__half2*)(g_wph + m * 65536 + off);
        d2[0] = __floats2half2_rn(v.x, v.y);
        d2[1] = __floats2half2_rn(v.z, v.w);
    }
}

// ---------------- fused conv: t2h = (relu(h@Wa+ba))@Wb + bb -----------------
// Block: 64 rows x full 256 cols, 256 threads (8 warps; warp = 32x64, 2 mi).
// ldmatrix fragments; cp.async W streaming; single sync per k-tile.
#define FBM 64
#define FAS16 264                  // b16 per As row (256 + 8; 528B -> rows 4 banks apart)
#define FBS16 264                  // b16 per Bs row
#define FA_B16 (FBM * FAS16)       // 16896 halves
#define FB_B16 (32 * FBS16)        // 8448 halves per buffer
#define FUSED_SMEM ((FA_B16 + 2 * FB_B16) * 2)   // 67584 bytes

// B tile kt: 32 k-rows x 256 halves; 1024 16B chunks / 256 threads
__device__ __forceinline__ void cpB(__half* dst, const __half* __restrict__ Wp,
                                    int kt, int tid) {
#pragma unroll
    for (int i = 0; i < 4; i++) {
        int l = tid + 256 * i;          // 0..1023
        int r  = l >> 5;                // k row 0..31
        int c8 = (l & 31) * 8;          // half col 0..248
        cp16(&dst[r * FBS16 + c8], Wp + (size_t)(kt * 32 + r) * 256 + c8);
    }
}

__global__ void __launch_bounds__(256, 2)
conv_fused(const float* __restrict__ A,
           const __half* __restrict__ Wa, const float* __restrict__ ba,
           const __half* __restrict__ Wb, const float* __restrict__ bb,
           __half2* __restrict__ out, int M) {
    extern __shared__ __half sm16[];
    __half* As = sm16;                     // 64 x 264 (A tile, then C1)
    __half* Bs = sm16 + FA_B16;            // 2 x 32 x 264

    int tid = threadIdx.x, lane = tid & 31, w = tid >> 5;
    int wr = (w & 1) * 32;                 // warp row offset (0/32)
    int wc = (w >> 1) * 64;                // warp col offset (0/64/128/192)
    int rowBase = blockIdx.x * FBM;
    int g = lane >> 2, t4 = lane & 3;
    int lr = lane & 7, q = lane >> 3;      // ldmatrix lane groups

    uint32_t as_u = (uint32_t)__cvta_generic_to_shared(As);
    uint32_t bs_u[2];
    bs_u[0] = (uint32_t)__cvta_generic_to_shared(Bs);
    bs_u[1] = bs_u[0] + FB_B16 * 2;

    // ldmatrix base addresses (byte offsets in shared space)
    // A tiles ordered: (m0-7,k0-7),(m8-15,k0-7),(m0-7,k8-15),(m8-15,k8-15)
    uint32_t aA0 = as_u + (uint32_t)(((wr + (q & 1) * 8 + lr) * FAS16 + (q >> 1) * 8) * 2);
    uint32_t aA1 = aA0 + 16 * FAS16 * 2;
    // B (trans) tiles: (k0-7,n0-7),(k8-15,n0-7),(k0-7,n8-15),(k8-15,n8-15)
    uint32_t bOff = (uint32_t)((((q & 1) * 8 + lr) * FBS16 + (q >> 1) * 8) * 2);

    // A tile: fp32 -> half smem (64 rows x 64 float4)
#pragma unroll
    for (int i = 0; i < 16; i++) {
        int l = tid + 256 * i;
        int r = l >> 6, c4 = l & 63;
        int grow = rowBase + r;
        float4 v = make_float4(0.f, 0.f, 0.f, 0.f);
        if (grow < M) v = *(const float4*)(A + (size_t)grow * HID + c4 * 4);
        __half2* row2 = (__half2*)(As + r * FAS16);
        row2[c4 * 2]     = __floats2half2_rn(v.x, v.y);
        row2[c4 * 2 + 1] = __floats2half2_rn(v.z, v.w);
    }

    float acc[2][8][4];
#pragma unroll
    for (int mi = 0; mi < 2; mi++)
#pragma unroll
        for (int ni = 0; ni < 8; ni++)
#pragma unroll
            for (int r = 0; r < 4; r++) acc[mi][ni][r] = 0.0f;

#pragma unroll
    for (int stage = 0; stage < 2; stage++) {
        const __half* Wp = (stage == 0) ? Wa : Wb;
        cpB(Bs, Wp, 0, tid);
        asm volatile("cp.async.commit_group;");
        int buf = 0;
#pragma unroll
        for (int kt = 0; kt < 8; kt++) {
            asm volatile("cp.async.wait_group 0;");
            __syncthreads();               // tile kt visible; prior reads of buf^1 done
            if (kt < 7) {
                cpB(Bs + (buf ^ 1) * FB_B16, Wp, kt + 1, tid);
                asm volatile("cp.async.commit_group;");
            }
            // compute tile kt from buf
#pragma unroll
            for (int s = 0; s < 2; s++) {
                uint32_t aoff = (uint32_t)((kt * 32 + s * 16) * 2);
                unsigned a0[4], a1[4];
                ldsm_x4(a0, aA0 + aoff);
                ldsm_x4(a1, aA1 + aoff);
                uint32_t bbase = bs_u[buf] + bOff + (uint32_t)(s * 16 * FBS16 * 2);
#pragma unroll
                for (int nj = 0; nj < 4; nj++) {
                    unsigned b[4];
                    ldsm_x4_trans(b, bbase + (uint32_t)((wc + nj * 16) * 2));
                    mma_f16(acc[0][nj * 2],     a0, b);
                    mma_f16(acc[0][nj * 2 + 1], a0, b + 2);
                    mma_f16(acc[1][nj * 2],     a1, b);
                    mma_f16(acc[1][nj * 2 + 1], a1, b + 2);
                }
            }
            buf ^= 1;
        }
        __syncthreads();                   // all stage reads done before As overwrite

        if (stage == 0) {
            // epilogue 1: C1 = relu(acc + ba) -> back into As; reset acc
#pragma unroll
            for (int mi = 0; mi < 2; mi++)
#pragma unroll
                for (int ni = 0; ni < 8; ni++) {
                    int col = wc + ni * 8 + t4 * 2;
                    float b0 = ba[col], b1 = ba[col + 1];
                    float v00 = fmaxf(acc[mi][ni][0] + b0, 0.f);
                    float v01 = fmaxf(acc[mi][ni][1] + b1, 0.f);
                    float v10 = fmaxf(acc[mi][ni][2] + b0, 0.f);
                    float v11 = fmaxf(acc[mi][ni][3] + b1, 0.f);
                    int r0 = wr + mi * 16 + g;
                    ((__half2*)(As + r0 * FAS16))[col >> 1]       = __floats2half2_rn(v00, v01);
                    ((__half2*)(As + (r0 + 8) * FAS16))[col >> 1] = __floats2half2_rn(v10, v11);
                    acc[mi][ni][0] = acc[mi][ni][1] = acc[mi][ni][2] = acc[mi][ni][3] = 0.0f;
                }
        }
    }

    // epilogue 2: out = acc + bb (half2 global store)
#pragma unroll
    for (int mi = 0; mi < 2; mi++)
#pragma unroll
        for (int ni = 0; ni < 8; ni++) {
            int col = wc + ni * 8 + t4 * 2;
            float b0 = bb[col], b1 = bb[col + 1];
            int r0 = rowBase + wr + mi * 16 + g;
            int r1 = r0 + 8;
            if (r0 < M)
                out[(size_t)r0 * (HID / 2) + (col >> 1)] =
                    __floats2half2_rn(acc[mi][ni][0] + b0, acc[mi][ni][1] + b1);
            if (r1 < M)
                out[(size_t)r1 * (HID / 2) + (col >> 1)] =
                    __floats2half2_rn(acc[mi][ni][2] + b0, acc[mi][ni][3] + b1);
        }
}

// ------- edge aggregation: warp-per-node float4 gather-max (R7 2-deep) ------
__global__ void agg_kernel() {
    const unsigned FULL = 0xffffffffu;
    int warp = threadIdx.x >> 5;
    int lane = threadIdx.x & 31;
    int n = blockIdx.x * 8 + warp;
    if (n >= N_NODES) return;

    int cnt = min(g_cur[n], ELL_CAP);
    const int* lst = g_ell + n * ELL_CAP;
    const float4* t2v = (const float4*)g_t2h;   // 32 float4 per row

    unsigned ninf = 0xFC00FC00u;
    __half2 mneg = *(__half2*)&ninf;
    __half2 m[8];
#pragma unroll
    for (int q = 0; q < 8; q++) m[q] = mneg;

    for (int base = 0; base < cnt; base += 32) {
        int e = base + lane;
        int idx = (e < cnt) ? lst[e] : 0;
        int c = min(32, cnt - base);
        int j = 0;
        for (; j + 2 <= c; j += 2) {
            int s0 = __shfl_sync(FULL, idx, j);
            int s1 = __shfl_sync(FULL, idx, j + 1);
            float4 v0 = t2v[s0 * 32 + lane];
            float4 v1 = t2v[s1 * 32 + lane];
            m[0] = __hmax2(m[0], *(__half2*)&v0.x);
            m[1] = __hmax2(m[1], *(__half2*)&v0.y);
            m[2] = __hmax2(m[2], *(__half2*)&v0.z);
            m[3] = __hmax2(m[3], *(__half2*)&v0.w);
            m[4] = __hmax2(m[4], *(__half2*)&v1.x);
            m[5] = __hmax2(m[5], *(__half2*)&v1.y);
            m[6] = __hmax2(m[6], *(__half2*)&v1.z);
            m[7] = __hmax2(m[7], *(__half2*)&v1.w);
        }
        if (j < c) {
            int s0 = __shfl_sync(FULL, idx, j);
            float4 v0 = t2v[s0 * 32 + lane];
            m[0] = __hmax2(m[0], *(__half2*)&v0.x);
            m[1] = __hmax2(m[1], *(__half2*)&v0.y);
            m[2] = __hmax2(m[2], *(__half2*)&v0.z);
            m[3] = __hmax2(m[3], *(__half2*)&v0.w);
        }
    }
#pragma unroll
    for (int q = 0; q < 4; q++) m[q] = __hmax2(m[q], m[q + 4]);

    float f[8];
#pragma unroll
    for (int q = 0; q < 4; q++) {
        float2 p = __half22float2(m[q]);
        f[2 * q]     = (cnt > 0) ? p.x : 0.0f;
        f[2 * q + 1] = (cnt > 0) ? p.y : 0.0f;
    }
    float4* hp = (float4*)(g_h + (size_t)n * HID) + lane * 2;
    float4 h0 = hp[0], h1 = hp[1];
    h0.x += silu(f[0]); h0.y += silu(f[1]); h0.z += silu(f[2]); h0.w += silu(f[3]);
    h1.x += silu(f[4]); h1.y += silu(f[5]); h1.z += silu(f[6]); h1.w += silu(f[7]);
    hp[0] = h0; hp[1] = h1;
}

// ------- global mean pool (batch sorted) + re-zero g_cur for next call -----
__global__ void pool_kernel(const int* __restrict__ batch,
                            float* __restrict__ out) {
    int g = blockIdx.x;          // 0..63
    int tid = threadIdx.x;       // 0..255 feature

    int lo = 0, hi = N_NODES;
    while (lo < hi) { int m = (lo + hi) >> 1; if (batch[m] < g) lo = m + 1; else hi = m; }
    int start = lo;
    lo = start; hi = N_NODES;
    while (lo < hi) { int m = (lo + hi) >> 1; if (batch[m] < g + 1) lo = m + 1; else hi = m; }
    int end = lo;

    float s = 0.0f;
    for (int n = start; n < end; n++)
        s += g_h[(size_t)n * HID + tid];
    float c = (float)(end - start);
    out[g * HID + tid] = s / fmaxf(c, 1.0f);

    int z = g * 256 + tid;       // 64*256 = 16384 >= N_NODES
    if (z < N_NODES) g_cur[z] = 0;
}

// ---------------- launch ----------------
extern "C" void kernel_launch(void* const* d_in, const int* in_sizes, int n_in,
                              void* d_out, int out_size) {
    const float* x     = (const float*)d_in[0];
    const int*   ei    = (const int*)d_in[1];
    const int*   batch = (const int*)d_in[2];
    const float* W_emb = (const float*)d_in[3];
    const float* b_emb = (const float*)d_in[4];
    const float* W1a   = (const float*)d_in[5];
    const float* b1a   = (const float*)d_in[6];
    const float* W1b   = (const float*)d_in[7];
    const float* b1b   = (const float*)d_in[8];
    const float* W2a   = (const float*)d_in[9];
    const float* b2a   = (const float*)d_in[10];
    const float* W2b   = (const float*)d_in[11];
    const float* b2b   = (const float*)d_in[12];
    float* out = (float*)d_out;

    const int* src = ei;
    const int* dst = ei + N_EDGES;

    float* h = nullptr; __half2* t2h = nullptr; __half* wph = nullptr;
    cudaGetSymbolAddress((void**)&h,   g_h);
    cudaGetSymbolAddress((void**)&t2h, g_t2h);
    cudaGetSymbolAddress((void**)&wph, g_wph);

    cudaFuncSetAttribute((const void*)conv_fused,
        cudaFuncAttributeMaxDynamicSharedMemorySize, FUSED_SMEM);

    // setup: ELL fill + embed + W pack in one grid
    setup_kernel<<<FILL_BLOCKS + EMBED_BLOCKS + PACK_BLOCKS, 256>>>(
        x, W_emb, b_emb, src, dst, W1a, W1b, W2a, W2b);

    int fgrid = (N_NODES + FBM - 1) / FBM;   // 157

    // conv 1 (fused MLP) + aggregation
    conv_fused<<<fgrid, 256, FUSED_SMEM>>>(h, wph, b1a, wph + 65536, b1b, t2h, N_NODES);
    agg_kernel<<<1250, 256>>>();

    // conv 2
    conv_fused<<<fgrid, 256, FUSED_SMEM>>>(h, wph + 131072, b2a, wph + 196608, b2b, t2h, N_NODES);
    agg_kernel<<<1250, 256>>>();

    // global mean pool (+ g_cur re-zero for next call)
    pool_kernel<<<N_GRAPHS, 256>>>(batch, out);
}